// round 1
// baseline (speedup 1.0000x reference)
#include <cuda_runtime.h>
#include <math.h>

#define Bsz 4
#define Nseq 1024
#define Dmod 1024
#define Hh 16
#define Dhd 64
#define Mtot (Bsz * Nseq)   // 4096
#define SCALE 0.03125f      // N^-0.5 = 1/32 (faithful quirk)

// Scratch (allocation-free rule: __device__ globals)
__device__ float g_q[Mtot * Dmod];
__device__ float g_k[Mtot * Dmod];
__device__ float g_v[Mtot * Dmod];
__device__ float g_o[Mtot * Dmod];  // [B,H,N,Dh] contiguous == scrambled [B,N,D]

// ---------------------------------------------------------------------------
// NT GEMM: C[M,N] = A[M,K] * W[N,K]^T + bias[N]
// 128x128 tile, K-step 8, 256 threads, 8x8 per-thread microtile.
// ---------------------------------------------------------------------------
__global__ __launch_bounds__(256) void gemm_nt_bias(
    const float* __restrict__ A, const float* __restrict__ W,
    const float* __restrict__ bias, float* __restrict__ C,
    int M, int N, int K)
{
    __shared__ float As[8][128];
    __shared__ float Ws[8][128];

    const int tid = threadIdx.x;
    const int tx = tid & 15;        // 0..15 -> 8 cols each
    const int ty = tid >> 4;        // 0..15 -> 8 rows each
    const int m0 = blockIdx.y * 128;
    const int n0 = blockIdx.x * 128;

    // loader: 256 threads x float4 = 1024 floats = 128 rows x 8 k
    const int lr = tid >> 1;        // 0..127
    const int lc = (tid & 1) * 4;   // 0 or 4
    const float* Ap = A + (size_t)(m0 + lr) * K + lc;
    const float* Wp = W + (size_t)(n0 + lr) * K + lc;

    float acc[8][8];
#pragma unroll
    for (int i = 0; i < 8; i++)
#pragma unroll
        for (int j = 0; j < 8; j++) acc[i][j] = 0.0f;

    for (int k0 = 0; k0 < K; k0 += 8) {
        float4 a4 = *(const float4*)(Ap + k0);
        float4 w4 = *(const float4*)(Wp + k0);
        As[lc + 0][lr] = a4.x; As[lc + 1][lr] = a4.y;
        As[lc + 2][lr] = a4.z; As[lc + 3][lr] = a4.w;
        Ws[lc + 0][lr] = w4.x; Ws[lc + 1][lr] = w4.y;
        Ws[lc + 2][lr] = w4.z; Ws[lc + 3][lr] = w4.w;
        __syncthreads();

#pragma unroll
        for (int k = 0; k < 8; k++) {
            float4 a0 = *(const float4*)&As[k][ty * 8];
            float4 a1 = *(const float4*)&As[k][ty * 8 + 4];
            float4 b0 = *(const float4*)&Ws[k][tx * 8];
            float4 b1 = *(const float4*)&Ws[k][tx * 8 + 4];
            float av[8] = {a0.x, a0.y, a0.z, a0.w, a1.x, a1.y, a1.z, a1.w};
            float bv[8] = {b0.x, b0.y, b0.z, b0.w, b1.x, b1.y, b1.z, b1.w};
#pragma unroll
            for (int i = 0; i < 8; i++)
#pragma unroll
                for (int j = 0; j < 8; j++)
                    acc[i][j] = fmaf(av[i], bv[j], acc[i][j]);
        }
        __syncthreads();
    }

    // epilogue: + bias, float4 stores
    float bv0[8];
#pragma unroll
    for (int j = 0; j < 8; j++) bv0[j] = bias[n0 + tx * 8 + j];

#pragma unroll
    for (int i = 0; i < 8; i++) {
        float* Cp = C + (size_t)(m0 + ty * 8 + i) * N + n0 + tx * 8;
        float4 o0, o1;
        o0.x = acc[i][0] + bv0[0]; o0.y = acc[i][1] + bv0[1];
        o0.z = acc[i][2] + bv0[2]; o0.w = acc[i][3] + bv0[3];
        o1.x = acc[i][4] + bv0[4]; o1.y = acc[i][5] + bv0[5];
        o1.z = acc[i][6] + bv0[6]; o1.w = acc[i][7] + bv0[7];
        *(float4*)(Cp + 0) = o0;
        *(float4*)(Cp + 4) = o1;
    }
}

// ---------------------------------------------------------------------------
// Flash-style attention per (b,h): Q tile 64 rows, loop 64-row KV tiles,
// online softmax. Output written in contiguous [B,H,N,Dh] layout (the
// reference's reshape quirk then reads this memory as [B,N,D] directly).
// ---------------------------------------------------------------------------
#define QP 65
#define KP 65
#define PP 65
#define VP 68
#define ATTN_SMEM ((64 * (QP + KP + PP + VP)) * 4)  // 67328 bytes

__global__ __launch_bounds__(256) void attn_kernel()
{
    extern __shared__ float sm[];
    float* Qs = sm;                  // 64 x QP
    float* Ks = Qs + 64 * QP;        // 64 x KP
    float* Ps = Ks + 64 * KP;        // 64 x PP
    float* Vs = Ps + 64 * PP;        // 64 x VP

    const int tid = threadIdx.x;
    const int tx = tid & 15;         // 4 kv-cols / dims
    const int ty = tid >> 4;         // 4 q-rows
    const int bh = blockIdx.y;       // 0..63
    const int b = bh / Hh;
    const int h = bh % Hh;
    const int qRow0 = blockIdx.x * 64;

    const float* qb = g_q + ((size_t)b * Nseq + qRow0) * Dmod + h * Dhd;
    const float* kbase = g_k + (size_t)b * Nseq * Dmod + h * Dhd;
    const float* vbase = g_v + (size_t)b * Nseq * Dmod + h * Dhd;

    // Load Q tile (pre-scaled by 1/32)
#pragma unroll
    for (int t = 0; t < 4; t++) {
        int s = tid + t * 256;           // 0..1023
        int r = s >> 4;
        int d = (s & 15) << 2;
        float4 q4 = *(const float4*)(qb + (size_t)r * Dmod + d);
        Qs[r * QP + d + 0] = q4.x * SCALE;
        Qs[r * QP + d + 1] = q4.y * SCALE;
        Qs[r * QP + d + 2] = q4.z * SCALE;
        Qs[r * QP + d + 3] = q4.w * SCALE;
    }

    float o[4][4];
    float mrow[4], lrow[4];
#pragma unroll
    for (int i = 0; i < 4; i++) {
        mrow[i] = -1e30f;
        lrow[i] = 0.0f;
#pragma unroll
        for (int j = 0; j < 4; j++) o[i][j] = 0.0f;
    }

    for (int kt = 0; kt < Nseq / 64; kt++) {
        __syncthreads();  // protect Ks/Vs/Ps from previous-iter readers (and Q on t=0)
        const float* kb = kbase + (size_t)(kt * 64) * Dmod;
        const float* vb = vbase + (size_t)(kt * 64) * Dmod;
#pragma unroll
        for (int t = 0; t < 4; t++) {
            int s = tid + t * 256;
            int r = s >> 4;
            int d = (s & 15) << 2;
            float4 k4 = *(const float4*)(kb + (size_t)r * Dmod + d);
            Ks[r * KP + d + 0] = k4.x; Ks[r * KP + d + 1] = k4.y;
            Ks[r * KP + d + 2] = k4.z; Ks[r * KP + d + 3] = k4.w;
            float4 v4 = *(const float4*)(vb + (size_t)r * Dmod + d);
            *(float4*)&Vs[r * VP + d] = v4;
        }
        __syncthreads();

        // S = (Q*scale) @ K^T : 4x4 per thread
        float s4[4][4];
#pragma unroll
        for (int i = 0; i < 4; i++)
#pragma unroll
            for (int j = 0; j < 4; j++) s4[i][j] = 0.0f;

#pragma unroll 16
        for (int k = 0; k < 64; k++) {
            float qv[4], kv[4];
#pragma unroll
            for (int i = 0; i < 4; i++) qv[i] = Qs[(ty * 4 + i) * QP + k];
#pragma unroll
            for (int j = 0; j < 4; j++) kv[j] = Ks[(tx * 4 + j) * KP + k];
#pragma unroll
            for (int i = 0; i < 4; i++)
#pragma unroll
                for (int j = 0; j < 4; j++)
                    s4[i][j] = fmaf(qv[i], kv[j], s4[i][j]);
        }

        // online softmax: row reductions across the 16 tx lanes
#pragma unroll
        for (int i = 0; i < 4; i++) {
            float mloc = fmaxf(fmaxf(s4[i][0], s4[i][1]), fmaxf(s4[i][2], s4[i][3]));
#pragma unroll
            for (int off = 8; off >= 1; off >>= 1)
                mloc = fmaxf(mloc, __shfl_xor_sync(0xffffffffu, mloc, off));
            float mnew = fmaxf(mrow[i], mloc);
            float alpha = __expf(mrow[i] - mnew);
            mrow[i] = mnew;
            lrow[i] *= alpha;
#pragma unroll
            for (int j = 0; j < 4; j++) o[i][j] *= alpha;

            float psum = 0.0f;
#pragma unroll
            for (int j = 0; j < 4; j++) {
                s4[i][j] = __expf(s4[i][j] - mnew);
                psum += s4[i][j];
            }
#pragma unroll
            for (int off = 8; off >= 1; off >>= 1)
                psum += __shfl_xor_sync(0xffffffffu, psum, off);
            lrow[i] += psum;

#pragma unroll
            for (int j = 0; j < 4; j++)
                Ps[(ty * 4 + i) * PP + tx * 4 + j] = s4[i][j];
        }
        __syncthreads();

        // O += P @ V
#pragma unroll 8
        for (int c = 0; c < 64; c++) {
            float4 v4 = *(const float4*)&Vs[c * VP + tx * 4];
#pragma unroll
            for (int i = 0; i < 4; i++) {
                float p = Ps[(ty * 4 + i) * PP + c];
                o[i][0] = fmaf(p, v4.x, o[i][0]);
                o[i][1] = fmaf(p, v4.y, o[i][1]);
                o[i][2] = fmaf(p, v4.z, o[i][2]);
                o[i][3] = fmaf(p, v4.w, o[i][3]);
            }
        }
    }

    // normalize + store in [B,H,N,Dh] contiguous layout
#pragma unroll
    for (int i = 0; i < 4; i++) {
        float inv = 1.0f / lrow[i];
        int n = qRow0 + ty * 4 + i;
        float* op = g_o + (((size_t)bh * Nseq) + n) * Dhd + tx * 4;
        float4 ov;
        ov.x = o[i][0] * inv; ov.y = o[i][1] * inv;
        ov.z = o[i][2] * inv; ov.w = o[i][3] * inv;
        *(float4*)op = ov;
    }
}

// ---------------------------------------------------------------------------
extern "C" void kernel_launch(void* const* d_in, const int* in_sizes, int n_in,
                              void* d_out, int out_size)
{
    const float* x  = (const float*)d_in[0];
    const float* Wq = (const float*)d_in[1];
    const float* bq = (const float*)d_in[2];
    const float* Wk = (const float*)d_in[3];
    const float* bk = (const float*)d_in[4];
    const float* Wv = (const float*)d_in[5];
    const float* bv = (const float*)d_in[6];
    const float* Wc = (const float*)d_in[7];
    const float* bc = (const float*)d_in[8];
    float* out = (float*)d_out;

    float* q; float* k; float* v; float* og;
    cudaGetSymbolAddress((void**)&q, g_q);
    cudaGetSymbolAddress((void**)&k, g_k);
    cudaGetSymbolAddress((void**)&v, g_v);
    cudaGetSymbolAddress((void**)&og, g_o);

    static bool attr_set = false;
    if (!attr_set) {
        cudaFuncSetAttribute(attn_kernel,
                             cudaFuncAttributeMaxDynamicSharedMemorySize,
                             ATTN_SMEM);
        attr_set = true;
    }

    dim3 gemm_grid(Dmod / 128, Mtot / 128);  // (8, 32)
    gemm_nt_bias<<<gemm_grid, 256>>>(x, Wq, bq, q, Mtot, Dmod, Dmod);
    gemm_nt_bias<<<gemm_grid, 256>>>(x, Wk, bk, k, Mtot, Dmod, Dmod);
    gemm_nt_bias<<<gemm_grid, 256>>>(x, Wv, bv, v, Mtot, Dmod, Dmod);

    dim3 attn_grid(Nseq / 64, Bsz * Hh);     // (16, 64)
    attn_kernel<<<attn_grid, 256, ATTN_SMEM>>>();

    gemm_nt_bias<<<gemm_grid, 256>>>(og, Wc, bc, out, Mtot, Dmod, Dmod);
}

// round 3
// speedup vs baseline: 1.4696x; 1.4696x over previous
#include <cuda_runtime.h>
#include <cuda_bf16.h>
#include <mma.h>
#include <math.h>
#include <stdint.h>

using namespace nvcuda;

#define Bsz 4
#define Nseq 1024
#define Dmod 1024
#define Hh 16
#define Dhd 64
#define Mtot (Bsz * Nseq)   // 4096
#define SCALE 0.03125f      // N^-0.5 = 1/32 (faithful quirk)

// ---------------------------------------------------------------------------
// Scratch (allocation-free rule: __device__ globals)
// ---------------------------------------------------------------------------
__device__ float g_q[Mtot * Dmod];
__device__ float g_k[Mtot * Dmod];
__device__ float g_v[Mtot * Dmod];

__device__ __nv_bfloat16 g_xhi[Mtot * Dmod];
__device__ __nv_bfloat16 g_xlo[Mtot * Dmod];
__device__ __nv_bfloat16 g_ohi[Mtot * Dmod];
__device__ __nv_bfloat16 g_olo[Mtot * Dmod];
__device__ __nv_bfloat16 g_wqhi[Dmod * Dmod];
__device__ __nv_bfloat16 g_wqlo[Dmod * Dmod];
__device__ __nv_bfloat16 g_wkhi[Dmod * Dmod];
__device__ __nv_bfloat16 g_wklo[Dmod * Dmod];
__device__ __nv_bfloat16 g_wvhi[Dmod * Dmod];
__device__ __nv_bfloat16 g_wvlo[Dmod * Dmod];
__device__ __nv_bfloat16 g_wchi[Dmod * Dmod];
__device__ __nv_bfloat16 g_wclo[Dmod * Dmod];

// ---------------------------------------------------------------------------
// helpers
// ---------------------------------------------------------------------------
__device__ __forceinline__ uint32_t smem_u32(const void* p) {
    uint32_t a;
    asm("{ .reg .u64 t; cvta.to.shared.u64 t, %1; cvt.u32.u64 %0, t; }"
        : "=r"(a) : "l"(p));
    return a;
}
__device__ __forceinline__ void cp16(uint32_t saddr, const void* g) {
    asm volatile("cp.async.cg.shared.global [%0], [%1], 16;" :: "r"(saddr), "l"(g));
}
#define CP_COMMIT() asm volatile("cp.async.commit_group;" ::: "memory")
#define CP_WAIT0()  asm volatile("cp.async.wait_group 0;" ::: "memory")
#define CP_WAIT1()  asm volatile("cp.async.wait_group 1;" ::: "memory")

// ---------------------------------------------------------------------------
// bf16 hi/lo split: hi = bf16(x), lo = bf16(x - hi)
// ---------------------------------------------------------------------------
__global__ __launch_bounds__(256) void split_bf16_kernel(
    const float* __restrict__ src,
    __nv_bfloat16* __restrict__ hi,
    __nv_bfloat16* __restrict__ lo,
    int n4)
{
    int i = blockIdx.x * blockDim.x + threadIdx.x;
    if (i >= n4) return;
    float4 v = ((const float4*)src)[i];
    __nv_bfloat16 h0 = __float2bfloat16_rn(v.x);
    __nv_bfloat16 h1 = __float2bfloat16_rn(v.y);
    __nv_bfloat16 h2 = __float2bfloat16_rn(v.z);
    __nv_bfloat16 h3 = __float2bfloat16_rn(v.w);
    __nv_bfloat16 l0 = __float2bfloat16_rn(v.x - __bfloat162float(h0));
    __nv_bfloat16 l1 = __float2bfloat16_rn(v.y - __bfloat162float(h1));
    __nv_bfloat16 l2 = __float2bfloat16_rn(v.z - __bfloat162float(h2));
    __nv_bfloat16 l3 = __float2bfloat16_rn(v.w - __bfloat162float(h3));
    __nv_bfloat162* hp = (__nv_bfloat162*)hi;
    __nv_bfloat162* lp = (__nv_bfloat162*)lo;
    hp[i * 2 + 0] = __nv_bfloat162(h0, h1);
    hp[i * 2 + 1] = __nv_bfloat162(h2, h3);
    lp[i * 2 + 0] = __nv_bfloat162(l0, l1);
    lp[i * 2 + 1] = __nv_bfloat162(l2, l3);
}

// ---------------------------------------------------------------------------
// wmma NT GEMM: C[M,N]tile(128x128) = (Ahi+Alo)[M,K] @ (Bhi+Blo)[N,K]^T + bias
// 3-product bf16 split, fp32 accum. K-stage 32, cp.async double buffer.
// smem pitch 40 bf16 (80B): ldmatrix row offsets stride 20 banks -> conflict-free.
// ---------------------------------------------------------------------------
#define GPITCH 40
#define TILE_E (128 * GPITCH)            // elements per operand tile (5120)
#define TILE_B (TILE_E * 2)              // 10240 bytes
#define STAGE_B (4 * TILE_B)             // 40960 bytes
#define GEMM_SMEM (2 * STAGE_B)          // 81920 bytes
#define NSTAGE (Dmod / 32)               // 32

__global__ __launch_bounds__(256) void gemm_wmma(
    const __nv_bfloat16* __restrict__ Ahi, const __nv_bfloat16* __restrict__ Alo,
    const __nv_bfloat16* __restrict__ Bhi, const __nv_bfloat16* __restrict__ Blo,
    const float* __restrict__ bias, float* __restrict__ C)
{
    extern __shared__ char dsm[];
    const int tid = threadIdx.x;
    const int w = tid >> 5;
    const int lane = tid & 31;
    const int m0 = blockIdx.y * 128;
    const int n0 = blockIdx.x * 128;
    const int wm = w >> 1;               // 0..3 -> m offset wm*32
    const int wn = w & 1;                // 0..1 -> n offset wn*64

    const uint32_t sb = smem_u32(dsm);

    // loader mapping: thread -> row (0..127), 2 float4 vectors of 8 bf16
    const int lrow = tid >> 1;
    const int v0 = (tid & 1) * 2;

    const __nv_bfloat16* ah = Ahi + (size_t)(m0 + lrow) * Dmod;
    const __nv_bfloat16* al = Alo + (size_t)(m0 + lrow) * Dmod;
    const __nv_bfloat16* bh = Bhi + (size_t)(n0 + lrow) * Dmod;
    const __nv_bfloat16* bl = Blo + (size_t)(n0 + lrow) * Dmod;

    wmma::fragment<wmma::accumulator, 16, 16, 16, float> acc[2][4];
#pragma unroll
    for (int i = 0; i < 2; i++)
#pragma unroll
        for (int j = 0; j < 4; j++) wmma::fill_fragment(acc[i][j], 0.0f);

    // stage loader
    auto load_stage = [&](int c, int s) {
        const int kc0 = c * 32;
        const uint32_t st = sb + s * STAGE_B;
#pragma unroll
        for (int vv = 0; vv < 2; vv++) {
            int v = v0 + vv;
            uint32_t so = (uint32_t)(lrow * (GPITCH * 2) + v * 16);
            cp16(st + 0 * TILE_B + so, ah + kc0 + v * 8);
            cp16(st + 1 * TILE_B + so, al + kc0 + v * 8);
            cp16(st + 2 * TILE_B + so, bh + kc0 + v * 8);
            cp16(st + 3 * TILE_B + so, bl + kc0 + v * 8);
        }
        CP_COMMIT();
    };

    load_stage(0, 0);

    for (int c = 0; c < NSTAGE; c++) {
        const int s = c & 1;
        if (c + 1 < NSTAGE) {
            load_stage(c + 1, s ^ 1);
            CP_WAIT1();
        } else {
            CP_WAIT0();
        }
        __syncthreads();

        const __nv_bfloat16* sAhi = (const __nv_bfloat16*)(dsm + s * STAGE_B);
        const __nv_bfloat16* sAlo = sAhi + TILE_E;
        const __nv_bfloat16* sBhi = sAlo + TILE_E;
        const __nv_bfloat16* sBlo = sBhi + TILE_E;

#pragma unroll
        for (int ks = 0; ks < 2; ks++) {
            wmma::fragment<wmma::matrix_a, 16, 16, 16, __nv_bfloat16, wmma::row_major> afh[2], afl[2];
            wmma::fragment<wmma::matrix_b, 16, 16, 16, __nv_bfloat16, wmma::col_major> bfh[4], bfl[4];
#pragma unroll
            for (int i = 0; i < 2; i++) {
                wmma::load_matrix_sync(afh[i], sAhi + (wm * 32 + i * 16) * GPITCH + ks * 16, GPITCH);
                wmma::load_matrix_sync(afl[i], sAlo + (wm * 32 + i * 16) * GPITCH + ks * 16, GPITCH);
            }
#pragma unroll
            for (int j = 0; j < 4; j++) {
                wmma::load_matrix_sync(bfh[j], sBhi + (wn * 64 + j * 16) * GPITCH + ks * 16, GPITCH);
                wmma::load_matrix_sync(bfl[j], sBlo + (wn * 64 + j * 16) * GPITCH + ks * 16, GPITCH);
            }
#pragma unroll
            for (int i = 0; i < 2; i++)
#pragma unroll
                for (int j = 0; j < 4; j++) {
                    wmma::mma_sync(acc[i][j], afh[i], bfh[j], acc[i][j]);
                    wmma::mma_sync(acc[i][j], afh[i], bfl[j], acc[i][j]);
                    wmma::mma_sync(acc[i][j], afl[i], bfh[j], acc[i][j]);
                }
        }
        __syncthreads();
    }

    // epilogue: stage accumulators through smem, add bias, coalesced stores
    float* ep = (float*)dsm + w * (32 * 68);
#pragma unroll
    for (int i = 0; i < 2; i++)
#pragma unroll
        for (int j = 0; j < 4; j++)
            wmma::store_matrix_sync(ep + i * 16 * 68 + j * 16, acc[i][j], 68, wmma::mem_row_major);
    __syncwarp();

    const float* brow = bias + n0 + wn * 64;
    float* crow = C + (size_t)(m0 + wm * 32 + lane) * Dmod + n0 + wn * 64;
#pragma unroll
    for (int cc = 0; cc < 64; cc += 4) {
        float4 vv = *(const float4*)(ep + lane * 68 + cc);
        vv.x += brow[cc + 0];
        vv.y += brow[cc + 1];
        vv.z += brow[cc + 2];
        vv.w += brow[cc + 3];
        *(float4*)(crow + cc) = vv;
    }
}

// ---------------------------------------------------------------------------
// Flash-style attention per (b,h). Writes output directly as bf16 hi/lo split
// in contiguous [B,H,N,Dh] layout (the reference's reshape quirk then reads
// this memory as [B,N,D] for the output projection).
// ---------------------------------------------------------------------------
#define QP 65
#define KP 65
#define PP 65
#define VP 68
#define ATTN_SMEM ((64 * (QP + KP + PP + VP)) * 4)  // 67328 bytes

__global__ __launch_bounds__(256) void attn_kernel()
{
    extern __shared__ float sm[];
    float* Qs = sm;
    float* Ks = Qs + 64 * QP;
    float* Ps = Ks + 64 * KP;
    float* Vs = Ps + 64 * PP;

    const int tid = threadIdx.x;
    const int tx = tid & 15;
    const int ty = tid >> 4;
    const int bh = blockIdx.y;
    const int b = bh / Hh;
    const int h = bh % Hh;
    const int qRow0 = blockIdx.x * 64;

    const float* qb = g_q + ((size_t)b * Nseq + qRow0) * Dmod + h * Dhd;
    const float* kbase = g_k + (size_t)b * Nseq * Dmod + h * Dhd;
    const float* vbase = g_v + (size_t)b * Nseq * Dmod + h * Dhd;

#pragma unroll
    for (int t = 0; t < 4; t++) {
        int s = tid + t * 256;
        int r = s >> 4;
        int d = (s & 15) << 2;
        float4 q4 = *(const float4*)(qb + (size_t)r * Dmod + d);
        Qs[r * QP + d + 0] = q4.x * SCALE;
        Qs[r * QP + d + 1] = q4.y * SCALE;
        Qs[r * QP + d + 2] = q4.z * SCALE;
        Qs[r * QP + d + 3] = q4.w * SCALE;
    }

    float o[4][4];
    float mrow[4], lrow[4];
#pragma unroll
    for (int i = 0; i < 4; i++) {
        mrow[i] = -1e30f;
        lrow[i] = 0.0f;
#pragma unroll
        for (int j = 0; j < 4; j++) o[i][j] = 0.0f;
    }

    for (int kt = 0; kt < Nseq / 64; kt++) {
        __syncthreads();
        const float* kb = kbase + (size_t)(kt * 64) * Dmod;
        const float* vb = vbase + (size_t)(kt * 64) * Dmod;
#pragma unroll
        for (int t = 0; t < 4; t++) {
            int s = tid + t * 256;
            int r = s >> 4;
            int d = (s & 15) << 2;
            float4 k4 = *(const float4*)(kb + (size_t)r * Dmod + d);
            Ks[r * KP + d + 0] = k4.x; Ks[r * KP + d + 1] = k4.y;
            Ks[r * KP + d + 2] = k4.z; Ks[r * KP + d + 3] = k4.w;
            float4 v4 = *(const float4*)(vb + (size_t)r * Dmod + d);
            *(float4*)&Vs[r * VP + d] = v4;
        }
        __syncthreads();

        float s4[4][4];
#pragma unroll
        for (int i = 0; i < 4; i++)
#pragma unroll
            for (int j = 0; j < 4; j++) s4[i][j] = 0.0f;

#pragma unroll 16
        for (int k = 0; k < 64; k++) {
            float qv[4], kv[4];
#pragma unroll
            for (int i = 0; i < 4; i++) qv[i] = Qs[(ty * 4 + i) * QP + k];
#pragma unroll
            for (int j = 0; j < 4; j++) kv[j] = Ks[(tx * 4 + j) * KP + k];
#pragma unroll
            for (int i = 0; i < 4; i++)
#pragma unroll
                for (int j = 0; j < 4; j++)
                    s4[i][j] = fmaf(qv[i], kv[j], s4[i][j]);
        }

#pragma unroll
        for (int i = 0; i < 4; i++) {
            float mloc = fmaxf(fmaxf(s4[i][0], s4[i][1]), fmaxf(s4[i][2], s4[i][3]));
#pragma unroll
            for (int off = 8; off >= 1; off >>= 1)
                mloc = fmaxf(mloc, __shfl_xor_sync(0xffffffffu, mloc, off));
            float mnew = fmaxf(mrow[i], mloc);
            float alpha = __expf(mrow[i] - mnew);
            mrow[i] = mnew;
            lrow[i] *= alpha;
#pragma unroll
            for (int j = 0; j < 4; j++) o[i][j] *= alpha;

            float psum = 0.0f;
#pragma unroll
            for (int j = 0; j < 4; j++) {
                s4[i][j] = __expf(s4[i][j] - mnew);
                psum += s4[i][j];
            }
#pragma unroll
            for (int off = 8; off >= 1; off >>= 1)
                psum += __shfl_xor_sync(0xffffffffu, psum, off);
            lrow[i] += psum;

#pragma unroll
            for (int j = 0; j < 4; j++)
                Ps[(ty * 4 + i) * PP + tx * 4 + j] = s4[i][j];
        }
        __syncthreads();

#pragma unroll 8
        for (int c = 0; c < 64; c++) {
            float4 v4 = *(const float4*)&Vs[c * VP + tx * 4];
#pragma unroll
            for (int i = 0; i < 4; i++) {
                float p = Ps[(ty * 4 + i) * PP + c];
                o[i][0] = fmaf(p, v4.x, o[i][0]);
                o[i][1] = fmaf(p, v4.y, o[i][1]);
                o[i][2] = fmaf(p, v4.z, o[i][2]);
                o[i][3] = fmaf(p, v4.w, o[i][3]);
            }
        }
    }

    // normalize + fused bf16 hi/lo split store, [B,H,N,Dh] contiguous
#pragma unroll
    for (int i = 0; i < 4; i++) {
        float inv = 1.0f / lrow[i];
        int n = qRow0 + ty * 4 + i;
        size_t off = (((size_t)bh * Nseq) + n) * Dhd + tx * 4;
        float vals[4];
        __nv_bfloat16 hv[4], lv[4];
#pragma unroll
        for (int j = 0; j < 4; j++) {
            vals[j] = o[i][j] * inv;
            hv[j] = __float2bfloat16_rn(vals[j]);
            lv[j] = __float2bfloat16_rn(vals[j] - __bfloat162float(hv[j]));
        }
        __nv_bfloat162* hp = (__nv_bfloat162*)(g_ohi + off);
        __nv_bfloat162* lp = (__nv_bfloat162*)(g_olo + off);
        hp[0] = __nv_bfloat162(hv[0], hv[1]);
        hp[1] = __nv_bfloat162(hv[2], hv[3]);
        lp[0] = __nv_bfloat162(lv[0], lv[1]);
        lp[1] = __nv_bfloat162(lv[2], lv[3]);
    }
}

// ---------------------------------------------------------------------------
extern "C" void kernel_launch(void* const* d_in, const int* in_sizes, int n_in,
                              void* d_out, int out_size)
{
    const float* x  = (const float*)d_in[0];
    const float* Wq = (const float*)d_in[1];
    const float* bq = (const float*)d_in[2];
    const float* Wk = (const float*)d_in[3];
    const float* bk = (const float*)d_in[4];
    const float* Wv = (const float*)d_in[5];
    const float* bv = (const float*)d_in[6];
    const float* Wc = (const float*)d_in[7];
    const float* bc = (const float*)d_in[8];
    float* out = (float*)d_out;

    float *q, *k, *v;
    cudaGetSymbolAddress((void**)&q, g_q);
    cudaGetSymbolAddress((void**)&k, g_k);
    cudaGetSymbolAddress((void**)&v, g_v);

    __nv_bfloat16 *xhi, *xlo, *ohi, *olo;
    __nv_bfloat16 *wqhi, *wqlo, *wkhi, *wklo, *wvhi, *wvlo, *wchi, *wclo;
    cudaGetSymbolAddress((void**)&xhi, g_xhi);
    cudaGetSymbolAddress((void**)&xlo, g_xlo);
    cudaGetSymbolAddress((void**)&ohi, g_ohi);
    cudaGetSymbolAddress((void**)&olo, g_olo);
    cudaGetSymbolAddress((void**)&wqhi, g_wqhi);
    cudaGetSymbolAddress((void**)&wqlo, g_wqlo);
    cudaGetSymbolAddress((void**)&wkhi, g_wkhi);
    cudaGetSymbolAddress((void**)&wklo, g_wklo);
    cudaGetSymbolAddress((void**)&wvhi, g_wvhi);
    cudaGetSymbolAddress((void**)&wvlo, g_wvlo);
    cudaGetSymbolAddress((void**)&wchi, g_wchi);
    cudaGetSymbolAddress((void**)&wclo, g_wclo);

    static bool attr_set = false;
    if (!attr_set) {
        cudaFuncSetAttribute(attn_kernel,
                             cudaFuncAttributeMaxDynamicSharedMemorySize, ATTN_SMEM);
        cudaFuncSetAttribute(gemm_wmma,
                             cudaFuncAttributeMaxDynamicSharedMemorySize, GEMM_SMEM);
        attr_set = true;
    }

    const int n4x = Mtot * Dmod / 4;   // 1M float4
    const int n4w = Dmod * Dmod / 4;   // 256K float4
    split_bf16_kernel<<<n4x / 256, 256>>>(x,  xhi, xlo, n4x);
    split_bf16_kernel<<<n4w / 256, 256>>>(Wq, wqhi, wqlo, n4w);
    split_bf16_kernel<<<n4w / 256, 256>>>(Wk, wkhi, wklo, n4w);
    split_bf16_kernel<<<n4w / 256, 256>>>(Wv, wvhi, wvlo, n4w);
    split_bf16_kernel<<<n4w / 256, 256>>>(Wc, wchi, wclo, n4w);

    dim3 gemm_grid(Dmod / 128, Mtot / 128);  // (8, 32)
    gemm_wmma<<<gemm_grid, 256, GEMM_SMEM>>>(xhi, xlo, wqhi, wqlo, bq, q);
    gemm_wmma<<<gemm_grid, 256, GEMM_SMEM>>>(xhi, xlo, wkhi, wklo, bk, k);
    gemm_wmma<<<gemm_grid, 256, GEMM_SMEM>>>(xhi, xlo, wvhi, wvlo, bv, v);

    dim3 attn_grid(Nseq / 64, Bsz * Hh);     // (16, 64)
    attn_kernel<<<attn_grid, 256, ATTN_SMEM>>>();

    gemm_wmma<<<gemm_grid, 256, GEMM_SMEM>>>(ohi, olo, wchi, wclo, bc, out);
}

// round 4
// speedup vs baseline: 1.9543x; 1.3299x over previous
#include <cuda_runtime.h>
#include <cuda_bf16.h>
#include <mma.h>
#include <math.h>
#include <stdint.h>

using namespace nvcuda;

#define Bsz 4
#define Nseq 1024
#define Dmod 1024
#define Hh 16
#define Dhd 64
#define Mtot (Bsz * Nseq)   // 4096
#define SCALE 0.03125f      // N^-0.5 = 1/32 (faithful quirk)

// ---------------------------------------------------------------------------
// Scratch (allocation-free rule: __device__ globals)
// ---------------------------------------------------------------------------
__device__ __nv_bfloat16 g_qhi[Mtot * Dmod];
__device__ __nv_bfloat16 g_qlo[Mtot * Dmod];
__device__ __nv_bfloat16 g_khi[Mtot * Dmod];
__device__ __nv_bfloat16 g_klo[Mtot * Dmod];
__device__ __nv_bfloat16 g_vhi[Mtot * Dmod];
__device__ __nv_bfloat16 g_vlo[Mtot * Dmod];

__device__ __nv_bfloat16 g_xhi[Mtot * Dmod];
__device__ __nv_bfloat16 g_xlo[Mtot * Dmod];
__device__ __nv_bfloat16 g_ohi[Mtot * Dmod];
__device__ __nv_bfloat16 g_olo[Mtot * Dmod];
__device__ __nv_bfloat16 g_wqhi[Dmod * Dmod];
__device__ __nv_bfloat16 g_wqlo[Dmod * Dmod];
__device__ __nv_bfloat16 g_wkhi[Dmod * Dmod];
__device__ __nv_bfloat16 g_wklo[Dmod * Dmod];
__device__ __nv_bfloat16 g_wvhi[Dmod * Dmod];
__device__ __nv_bfloat16 g_wvlo[Dmod * Dmod];
__device__ __nv_bfloat16 g_wchi[Dmod * Dmod];
__device__ __nv_bfloat16 g_wclo[Dmod * Dmod];

// ---------------------------------------------------------------------------
// helpers
// ---------------------------------------------------------------------------
__device__ __forceinline__ uint32_t smem_u32(const void* p) {
    uint32_t a;
    asm("{ .reg .u64 t; cvta.to.shared.u64 t, %1; cvt.u32.u64 %0, t; }"
        : "=r"(a) : "l"(p));
    return a;
}
__device__ __forceinline__ void cp16(uint32_t saddr, const void* g) {
    asm volatile("cp.async.cg.shared.global [%0], [%1], 16;" :: "r"(saddr), "l"(g));
}
#define CP_COMMIT() asm volatile("cp.async.commit_group;" ::: "memory")
#define CP_WAIT0()  asm volatile("cp.async.wait_group 0;" ::: "memory")
#define CP_WAIT1()  asm volatile("cp.async.wait_group 1;" ::: "memory")

// fast exp on the FMA pipe: exp(x) = 2^(x*log2e), magic-number rounding +
// degree-6 Taylor of 2^t on t in [-0.5,0.5] (rel err ~1e-7). No MUFU.
__device__ __forceinline__ float exp_fast(float x) {
    float y = x * 1.44269504088896f;
    float z = y + 12582912.0f;                      // round y to nearest int
    int   n = __float_as_int(z) - 0x4B400000;
    float r = z - 12582912.0f;
    float t = y - r;                                // [-0.5, 0.5]
    float p =            0.00015403530393381609f;
    p = fmaf(p, t, 0.0013333558146428443f);
    p = fmaf(p, t, 0.009618129107628477f);
    p = fmaf(p, t, 0.05550410866482158f);
    p = fmaf(p, t, 0.2402265069591007f);
    p = fmaf(p, t, 0.6931471805599453f);
    p = fmaf(p, t, 1.0f);
    return __int_as_float(__float_as_int(p) + (n << 23));
}

// split float4 into truncated-bf16 hi (exact bits) + rn-bf16 lo, store 4+4
__device__ __forceinline__ void split_store4(float4 v,
                                             __nv_bfloat16* hp, __nv_bfloat16* lp) {
    uint32_t ax = __float_as_uint(v.x) & 0xFFFF0000u;
    uint32_t ay = __float_as_uint(v.y) & 0xFFFF0000u;
    uint32_t az = __float_as_uint(v.z) & 0xFFFF0000u;
    uint32_t aw = __float_as_uint(v.w) & 0xFFFF0000u;
    float lx = v.x - __uint_as_float(ax);
    float ly = v.y - __uint_as_float(ay);
    float lz = v.z - __uint_as_float(az);
    float lw = v.w - __uint_as_float(aw);
    uint2 h;
    h.x = __byte_perm(ax, ay, 0x7632);
    h.y = __byte_perm(az, aw, 0x7632);
    *(uint2*)hp = h;
    __nv_bfloat162 l01 = __float22bfloat162_rn(make_float2(lx, ly));
    __nv_bfloat162 l23 = __float22bfloat162_rn(make_float2(lz, lw));
    uint2 l;
    l.x = *(uint32_t*)&l01;
    l.y = *(uint32_t*)&l23;
    *(uint2*)lp = l;
}

// ---------------------------------------------------------------------------
// bf16 hi/lo split kernel (x and the 4 weights)
// ---------------------------------------------------------------------------
__global__ __launch_bounds__(256) void split_bf16_kernel(
    const float* __restrict__ src,
    __nv_bfloat16* __restrict__ hi,
    __nv_bfloat16* __restrict__ lo,
    int n4)
{
    int i = blockIdx.x * blockDim.x + threadIdx.x;
    if (i >= n4) return;
    float4 v = ((const float4*)src)[i];
    split_store4(v, hi + i * 4, lo + i * 4);
}

// ---------------------------------------------------------------------------
// wmma NT GEMM: C tile(128x128) = (Ahi+Alo)[M,K] @ (Bhi+Blo)[N,K]^T + bias
// Output either fp32 (Cf) or scaled hi/lo bf16 split (outHi/outLo).
// ---------------------------------------------------------------------------
#define GPITCH 40
#define TILE_E (128 * GPITCH)
#define TILE_B (TILE_E * 2)
#define STAGE_B (4 * TILE_B)
#define GEMM_SMEM (2 * STAGE_B)          // 81920 bytes
#define NSTAGE (Dmod / 32)               // 32

__global__ __launch_bounds__(256) void gemm_wmma(
    const __nv_bfloat16* __restrict__ Ahi, const __nv_bfloat16* __restrict__ Alo,
    const __nv_bfloat16* __restrict__ Bhi, const __nv_bfloat16* __restrict__ Blo,
    const float* __restrict__ bias,
    float* __restrict__ Cf,
    __nv_bfloat16* __restrict__ outHi, __nv_bfloat16* __restrict__ outLo,
    float oscale)
{
    extern __shared__ char dsm[];
    const int tid = threadIdx.x;
    const int w = tid >> 5;
    const int lane = tid & 31;
    const int m0 = blockIdx.y * 128;
    const int n0 = blockIdx.x * 128;
    const int wm = w >> 1;
    const int wn = w & 1;

    const uint32_t sb = smem_u32(dsm);
    const int lrow = tid >> 1;
    const int v0 = (tid & 1) * 2;

    const __nv_bfloat16* ah = Ahi + (size_t)(m0 + lrow) * Dmod;
    const __nv_bfloat16* al = Alo + (size_t)(m0 + lrow) * Dmod;
    const __nv_bfloat16* bh = Bhi + (size_t)(n0 + lrow) * Dmod;
    const __nv_bfloat16* bl = Blo + (size_t)(n0 + lrow) * Dmod;

    wmma::fragment<wmma::accumulator, 16, 16, 16, float> acc[2][4];
#pragma unroll
    for (int i = 0; i < 2; i++)
#pragma unroll
        for (int j = 0; j < 4; j++) wmma::fill_fragment(acc[i][j], 0.0f);

    auto load_stage = [&](int c, int s) {
        const int kc0 = c * 32;
        const uint32_t st = sb + s * STAGE_B;
#pragma unroll
        for (int vv = 0; vv < 2; vv++) {
            int v = v0 + vv;
            uint32_t so = (uint32_t)(lrow * (GPITCH * 2) + v * 16);
            cp16(st + 0 * TILE_B + so, ah + kc0 + v * 8);
            cp16(st + 1 * TILE_B + so, al + kc0 + v * 8);
            cp16(st + 2 * TILE_B + so, bh + kc0 + v * 8);
            cp16(st + 3 * TILE_B + so, bl + kc0 + v * 8);
        }
        CP_COMMIT();
    };

    load_stage(0, 0);

    for (int c = 0; c < NSTAGE; c++) {
        const int s = c & 1;
        if (c + 1 < NSTAGE) {
            load_stage(c + 1, s ^ 1);
            CP_WAIT1();
        } else {
            CP_WAIT0();
        }
        __syncthreads();

        const __nv_bfloat16* sAhi = (const __nv_bfloat16*)(dsm + s * STAGE_B);
        const __nv_bfloat16* sAlo = sAhi + TILE_E;
        const __nv_bfloat16* sBhi = sAlo + TILE_E;
        const __nv_bfloat16* sBlo = sBhi + TILE_E;

#pragma unroll
        for (int ks = 0; ks < 2; ks++) {
            wmma::fragment<wmma::matrix_a, 16, 16, 16, __nv_bfloat16, wmma::row_major> afh[2], afl[2];
            wmma::fragment<wmma::matrix_b, 16, 16, 16, __nv_bfloat16, wmma::col_major> bfh[4], bfl[4];
#pragma unroll
            for (int i = 0; i < 2; i++) {
                wmma::load_matrix_sync(afh[i], sAhi + (wm * 32 + i * 16) * GPITCH + ks * 16, GPITCH);
                wmma::load_matrix_sync(afl[i], sAlo + (wm * 32 + i * 16) * GPITCH + ks * 16, GPITCH);
            }
#pragma unroll
            for (int j = 0; j < 4; j++) {
                wmma::load_matrix_sync(bfh[j], sBhi + (wn * 64 + j * 16) * GPITCH + ks * 16, GPITCH);
                wmma::load_matrix_sync(bfl[j], sBlo + (wn * 64 + j * 16) * GPITCH + ks * 16, GPITCH);
            }
#pragma unroll
            for (int i = 0; i < 2; i++)
#pragma unroll
                for (int j = 0; j < 4; j++) {
                    wmma::mma_sync(acc[i][j], afh[i], bfh[j], acc[i][j]);
                    wmma::mma_sync(acc[i][j], afh[i], bfl[j], acc[i][j]);
                    wmma::mma_sync(acc[i][j], afl[i], bfh[j], acc[i][j]);
                }
        }
        __syncthreads();
    }

    // epilogue via smem stage
    float* ep = (float*)dsm + w * (32 * 68);
#pragma unroll
    for (int i = 0; i < 2; i++)
#pragma unroll
        for (int j = 0; j < 4; j++)
            wmma::store_matrix_sync(ep + i * 16 * 68 + j * 16, acc[i][j], 68, wmma::mem_row_major);
    __syncwarp();

    const float* brow = bias + n0 + wn * 64;
    const size_t rowbase = (size_t)(m0 + wm * 32 + lane) * Dmod + n0 + wn * 64;

    if (Cf != nullptr) {
        float* crow = Cf + rowbase;
#pragma unroll
        for (int cc = 0; cc < 64; cc += 4) {
            float4 vv = *(const float4*)(ep + lane * 68 + cc);
            vv.x += brow[cc + 0];
            vv.y += brow[cc + 1];
            vv.z += brow[cc + 2];
            vv.w += brow[cc + 3];
            *(float4*)(crow + cc) = vv;
        }
    } else {
#pragma unroll
        for (int cc = 0; cc < 64; cc += 4) {
            float4 vv = *(const float4*)(ep + lane * 68 + cc);
            vv.x = (vv.x + brow[cc + 0]) * oscale;
            vv.y = (vv.y + brow[cc + 1]) * oscale;
            vv.z = (vv.z + brow[cc + 2]) * oscale;
            vv.w = (vv.w + brow[cc + 3]) * oscale;
            split_store4(vv, outHi + rowbase + cc, outLo + rowbase + cc);
        }
    }
}

// ---------------------------------------------------------------------------
// Tensor-core flash-ish attention (no max subtraction: scores are tiny by the
// 1/32 quirk-scale; exp cannot overflow). Per CTA: 64 q rows of one (b,h).
// S=Q@K^T via wmma (bf16 hi/lo 3-product), exp via FMA-pipe poly, P hi/lo
// split, O += P@V via wmma (3-product). Normalize by row-sum at the end.
// Output written as hi/lo bf16 in contiguous [B,H,N,Dh] layout.
// ---------------------------------------------------------------------------
#define QT 64
#define KTILE 64
#define APITCH 72
#define SPITCH 68
#define TB2 (64 * APITCH * 2)       // 9216 bytes per bf16 tile
#define SM_QHI 0
#define SM_QLO (1 * TB2)
#define SM_KHI (2 * TB2)
#define SM_KLO (3 * TB2)
#define SM_VHI (4 * TB2)
#define SM_VLO (5 * TB2)
#define SM_PHI (6 * TB2)
#define SM_PLO (7 * TB2)
#define SM_S   (8 * TB2)            // 64 x 68 f32 = 17408 bytes
#define ATTN_SMEM (8 * TB2 + 64 * SPITCH * 4)   // 91136 bytes

__global__ __launch_bounds__(128) void attn_tc_kernel()
{
    extern __shared__ char asm_[];
    const uint32_t sb = smem_u32(asm_);
    const int tid = threadIdx.x;
    const int w = tid >> 5;
    const int lane = tid & 31;
    const int bh = blockIdx.y;
    const int b = bh / Hh;
    const int h = bh % Hh;
    const int qRow0 = blockIdx.x * QT;

    const size_t headoff = (size_t)h * Dhd;
    const __nv_bfloat16* qh_g = g_qhi + ((size_t)b * Nseq + qRow0) * Dmod + headoff;
    const __nv_bfloat16* ql_g = g_qlo + ((size_t)b * Nseq + qRow0) * Dmod + headoff;
    const __nv_bfloat16* kh_g = g_khi + (size_t)b * Nseq * Dmod + headoff;
    const __nv_bfloat16* kl_g = g_klo + (size_t)b * Nseq * Dmod + headoff;
    const __nv_bfloat16* vh_g = g_vhi + (size_t)b * Nseq * Dmod + headoff;
    const __nv_bfloat16* vl_g = g_vlo + (size_t)b * Nseq * Dmod + headoff;

    // tile loader: 64 rows x 64 bf16 (row stride Dmod) -> pitch-72 smem
    auto load_tile = [&](uint32_t dst, const __nv_bfloat16* g) {
#pragma unroll
        for (int t = 0; t < 4; t++) {
            int id = tid + t * 128;
            int row = id >> 3;
            int c8 = (id & 7) * 8;
            cp16(dst + (uint32_t)(row * APITCH + c8) * 2, g + (size_t)row * Dmod + c8);
        }
    };

    // Q once + first K/V
    load_tile(sb + SM_QHI, qh_g);
    load_tile(sb + SM_QLO, ql_g);
    load_tile(sb + SM_KHI, kh_g);
    load_tile(sb + SM_KLO, kl_g);
    load_tile(sb + SM_VHI, vh_g);
    load_tile(sb + SM_VLO, vl_g);
    CP_COMMIT();
    CP_WAIT0();
    __syncthreads();

    // hoist Q fragments (warp strip rows [16w,16w+16), 4 k-steps over d)
    wmma::fragment<wmma::matrix_a, 16, 16, 16, __nv_bfloat16, wmma::row_major> qfh[4], qfl[4];
    {
        const __nv_bfloat16* Qh = (const __nv_bfloat16*)(asm_ + SM_QHI) + w * 16 * APITCH;
        const __nv_bfloat16* Ql = (const __nv_bfloat16*)(asm_ + SM_QLO) + w * 16 * APITCH;
#pragma unroll
        for (int ks = 0; ks < 4; ks++) {
            wmma::load_matrix_sync(qfh[ks], Qh + ks * 16, APITCH);
            wmma::load_matrix_sync(qfl[ks], Ql + ks * 16, APITCH);
        }
    }

    wmma::fragment<wmma::accumulator, 16, 16, 16, float> oacc[4];
#pragma unroll
    for (int dt = 0; dt < 4; dt++) wmma::fill_fragment(oacc[dt], 0.0f);

    const int rl = lane >> 1;            // local row 0..15
    const int c0 = (lane & 1) * 32;      // col half
    float lsum = 0.0f;

    float* Srow = (float*)(asm_ + SM_S) + (w * 16 + rl) * SPITCH + c0;
    __nv_bfloat16* Ph_row = (__nv_bfloat16*)(asm_ + SM_PHI) + (w * 16 + rl) * APITCH + c0;
    __nv_bfloat16* Pl_row = (__nv_bfloat16*)(asm_ + SM_PLO) + (w * 16 + rl) * APITCH + c0;

    for (int kt = 0; kt < Nseq / KTILE; kt++) {
        // ---- S = Q @ K^T (warp-private 16x64 strip) ----
        wmma::fragment<wmma::accumulator, 16, 16, 16, float> sacc[4];
#pragma unroll
        for (int jt = 0; jt < 4; jt++) wmma::fill_fragment(sacc[jt], 0.0f);

        const __nv_bfloat16* Kh = (const __nv_bfloat16*)(asm_ + SM_KHI);
        const __nv_bfloat16* Kl = (const __nv_bfloat16*)(asm_ + SM_KLO);
#pragma unroll
        for (int jt = 0; jt < 4; jt++) {
#pragma unroll
            for (int ks = 0; ks < 4; ks++) {
                wmma::fragment<wmma::matrix_b, 16, 16, 16, __nv_bfloat16, wmma::col_major> kfh, kfl;
                wmma::load_matrix_sync(kfh, Kh + (jt * 16) * APITCH + ks * 16, APITCH);
                wmma::load_matrix_sync(kfl, Kl + (jt * 16) * APITCH + ks * 16, APITCH);
                wmma::mma_sync(sacc[jt], qfh[ks], kfh, sacc[jt]);
                wmma::mma_sync(sacc[jt], qfh[ks], kfl, sacc[jt]);
                wmma::mma_sync(sacc[jt], qfl[ks], kfh, sacc[jt]);
            }
        }
        {
            float* Sst = (float*)(asm_ + SM_S) + (w * 16) * SPITCH;
#pragma unroll
            for (int jt = 0; jt < 4; jt++)
                wmma::store_matrix_sync(Sst + jt * 16, sacc[jt], SPITCH, wmma::mem_row_major);
        }
        __syncwarp();

        // ---- exp + row-sum + P hi/lo split (warp-private strip) ----
#pragma unroll
        for (int cc = 0; cc < 32; cc += 4) {
            float4 s4 = *(const float4*)(Srow + cc);
            float4 e4;
            e4.x = exp_fast(s4.x);
            e4.y = exp_fast(s4.y);
            e4.z = exp_fast(s4.z);
            e4.w = exp_fast(s4.w);
            lsum += (e4.x + e4.y) + (e4.z + e4.w);
            split_store4(e4, Ph_row + cc, Pl_row + cc);
        }
        __syncwarp();

        // ---- O += P @ V ----
        const __nv_bfloat16* Ph = (const __nv_bfloat16*)(asm_ + SM_PHI) + w * 16 * APITCH;
        const __nv_bfloat16* Pl = (const __nv_bfloat16*)(asm_ + SM_PLO) + w * 16 * APITCH;
        const __nv_bfloat16* Vh = (const __nv_bfloat16*)(asm_ + SM_VHI);
        const __nv_bfloat16* Vl = (const __nv_bfloat16*)(asm_ + SM_VLO);
#pragma unroll
        for (int kk = 0; kk < 4; kk++) {
            wmma::fragment<wmma::matrix_a, 16, 16, 16, __nv_bfloat16, wmma::row_major> pfh, pfl;
            wmma::load_matrix_sync(pfh, Ph + kk * 16, APITCH);
            wmma::load_matrix_sync(pfl, Pl + kk * 16, APITCH);
#pragma unroll
            for (int dt = 0; dt < 4; dt++) {
                wmma::fragment<wmma::matrix_b, 16, 16, 16, __nv_bfloat16, wmma::row_major> vfh, vfl;
                wmma::load_matrix_sync(vfh, Vh + (kk * 16) * APITCH + dt * 16, APITCH);
                wmma::load_matrix_sync(vfl, Vl + (kk * 16) * APITCH + dt * 16, APITCH);
                wmma::mma_sync(oacc[dt], pfh, vfh, oacc[dt]);
                wmma::mma_sync(oacc[dt], pfh, vfl, oacc[dt]);
                wmma::mma_sync(oacc[dt], pfl, vfh, oacc[dt]);
            }
        }

        // ---- next K/V tiles ----
        __syncthreads();
        if (kt + 1 < Nseq / KTILE) {
            const size_t koff = (size_t)(kt + 1) * KTILE * Dmod;
            load_tile(sb + SM_KHI, kh_g + koff);
            load_tile(sb + SM_KLO, kl_g + koff);
            load_tile(sb + SM_VHI, vh_g + koff);
            load_tile(sb + SM_VLO, vl_g + koff);
            CP_COMMIT();
            CP_WAIT0();
            __syncthreads();
        }
    }

    // ---- epilogue: stage O, normalize by row sum, hi/lo split store ----
    {
        float* Ost = (float*)(asm_ + SM_S) + (w * 16) * SPITCH;
#pragma unroll
        for (int dt = 0; dt < 4; dt++)
            wmma::store_matrix_sync(Ost + dt * 16, oacc[dt], SPITCH, wmma::mem_row_major);
    }
    __syncwarp();

    float ltot = lsum + __shfl_xor_sync(0xffffffffu, lsum, 1);
    float inv = 1.0f / ltot;

    const int n = qRow0 + w * 16 + rl;
    const size_t obase = (((size_t)bh * Nseq) + n) * Dhd + c0;
    const float* Orow = (float*)(asm_ + SM_S) + (w * 16 + rl) * SPITCH + c0;
#pragma unroll
    for (int cc = 0; cc < 32; cc += 4) {
        float4 v4 = *(const float4*)(Orow + cc);
        v4.x *= inv; v4.y *= inv; v4.z *= inv; v4.w *= inv;
        split_store4(v4, g_ohi + obase + cc, g_olo + obase + cc);
    }
}

// ---------------------------------------------------------------------------
extern "C" void kernel_launch(void* const* d_in, const int* in_sizes, int n_in,
                              void* d_out, int out_size)
{
    const float* x  = (const float*)d_in[0];
    const float* Wq = (const float*)d_in[1];
    const float* bq = (const float*)d_in[2];
    const float* Wk = (const float*)d_in[3];
    const float* bk = (const float*)d_in[4];
    const float* Wv = (const float*)d_in[5];
    const float* bv = (const float*)d_in[6];
    const float* Wc = (const float*)d_in[7];
    const float* bc = (const float*)d_in[8];
    float* out = (float*)d_out;

    __nv_bfloat16 *qhi, *qlo, *khi, *klo, *vhi, *vlo;
    __nv_bfloat16 *xhi, *xlo, *ohi, *olo;
    __nv_bfloat16 *wqhi, *wqlo, *wkhi, *wklo, *wvhi, *wvlo, *wchi, *wclo;
    cudaGetSymbolAddress((void**)&qhi, g_qhi);
    cudaGetSymbolAddress((void**)&qlo, g_qlo);
    cudaGetSymbolAddress((void**)&khi, g_khi);
    cudaGetSymbolAddress((void**)&klo, g_klo);
    cudaGetSymbolAddress((void**)&vhi, g_vhi);
    cudaGetSymbolAddress((void**)&vlo, g_vlo);
    cudaGetSymbolAddress((void**)&xhi, g_xhi);
    cudaGetSymbolAddress((void**)&xlo, g_xlo);
    cudaGetSymbolAddress((void**)&ohi, g_ohi);
    cudaGetSymbolAddress((void**)&olo, g_olo);
    cudaGetSymbolAddress((void**)&wqhi, g_wqhi);
    cudaGetSymbolAddress((void**)&wqlo, g_wqlo);
    cudaGetSymbolAddress((void**)&wkhi, g_wkhi);
    cudaGetSymbolAddress((void**)&wklo, g_wklo);
    cudaGetSymbolAddress((void**)&wvhi, g_wvhi);
    cudaGetSymbolAddress((void**)&wvlo, g_wvlo);
    cudaGetSymbolAddress((void**)&wchi, g_wchi);
    cudaGetSymbolAddress((void**)&wclo, g_wclo);

    static bool attr_set = false;
    if (!attr_set) {
        cudaFuncSetAttribute(attn_tc_kernel,
                             cudaFuncAttributeMaxDynamicSharedMemorySize, ATTN_SMEM);
        cudaFuncSetAttribute(gemm_wmma,
                             cudaFuncAttributeMaxDynamicSharedMemorySize, GEMM_SMEM);
        attr_set = true;
    }

    const int n4x = Mtot * Dmod / 4;
    const int n4w = Dmod * Dmod / 4;
    split_bf16_kernel<<<n4x / 256, 256>>>(x,  xhi, xlo, n4x);
    split_bf16_kernel<<<n4w / 256, 256>>>(Wq, wqhi, wqlo, n4w);
    split_bf16_kernel<<<n4w / 256, 256>>>(Wk, wkhi, wklo, n4w);
    split_bf16_kernel<<<n4w / 256, 256>>>(Wv, wvhi, wvlo, n4w);
    split_bf16_kernel<<<n4w / 256, 256>>>(Wc, wchi, wclo, n4w);

    dim3 gemm_grid(Dmod / 128, Mtot / 128);  // (8, 32)
    // Q scaled by exact 1/32 (power of two) before split
    gemm_wmma<<<gemm_grid, 256, GEMM_SMEM>>>(xhi, xlo, wqhi, wqlo, bq,
                                             nullptr, qhi, qlo, SCALE);
    gemm_wmma<<<gemm_grid, 256, GEMM_SMEM>>>(xhi, xlo, wkhi, wklo, bk,
                                             nullptr, khi, klo, 1.0f);
    gemm_wmma<<<gemm_grid, 256, GEMM_SMEM>>>(xhi, xlo, wvhi, wvlo, bv,
                                             nullptr, vhi, vlo, 1.0f);

    dim3 attn_grid(Nseq / QT, Bsz * Hh);     // (16, 64)
    attn_tc_kernel<<<attn_grid, 128, ATTN_SMEM>>>();

    gemm_wmma<<<gemm_grid, 256, GEMM_SMEM>>>(ohi, olo, wchi, wclo, bc,
                                             out, nullptr, nullptr, 1.0f);
}

// round 5
// speedup vs baseline: 2.8231x; 1.4445x over previous
#include <cuda_runtime.h>
#include <cuda_bf16.h>
#include <cuda_fp16.h>
#include <mma.h>
#include <math.h>
#include <stdint.h>

using namespace nvcuda;

#define Bsz 4
#define Nseq 1024
#define Dmod 1024
#define Hh 16
#define Dhd 64
#define Mtot (Bsz * Nseq)   // 4096
#define SCALE 0.03125f      // N^-0.5 = 1/32 (faithful quirk)

// ---------------------------------------------------------------------------
// Scratch (allocation-free rule: __device__ globals)
// ---------------------------------------------------------------------------
__device__ __half g_qf[Mtot * Dmod];      // fp16 q (pre-scaled by 1/32)
__device__ __half g_kf[Mtot * Dmod];      // fp16 k
__device__ __half g_vhf[Mtot * Dmod];     // fp16 v hi
__device__ __half g_vlf[Mtot * Dmod];     // fp16 v lo
__device__ __half g_xf[Mtot * Dmod];      // fp16 x
__device__ __half g_wqf[Dmod * Dmod];
__device__ __half g_wkf[Dmod * Dmod];

__device__ __nv_bfloat16 g_xhi[Mtot * Dmod];
__device__ __nv_bfloat16 g_xlo[Mtot * Dmod];
__device__ __nv_bfloat16 g_ohi[Mtot * Dmod];
__device__ __nv_bfloat16 g_olo[Mtot * Dmod];
__device__ __nv_bfloat16 g_wvhi[Dmod * Dmod];
__device__ __nv_bfloat16 g_wvlo[Dmod * Dmod];
__device__ __nv_bfloat16 g_wchi[Dmod * Dmod];
__device__ __nv_bfloat16 g_wclo[Dmod * Dmod];

// ---------------------------------------------------------------------------
// helpers
// ---------------------------------------------------------------------------
__device__ __forceinline__ uint32_t smem_u32(const void* p) {
    uint32_t a;
    asm("{ .reg .u64 t; cvta.to.shared.u64 t, %1; cvt.u32.u64 %0, t; }"
        : "=r"(a) : "l"(p));
    return a;
}
__device__ __forceinline__ void cp16(uint32_t saddr, const void* g) {
    asm volatile("cp.async.cg.shared.global [%0], [%1], 16;" :: "r"(saddr), "l"(g));
}
#define CP_COMMIT() asm volatile("cp.async.commit_group;" ::: "memory")
#define CP_WAIT0()  asm volatile("cp.async.wait_group 0;" ::: "memory")
#define CP_WAIT1()  asm volatile("cp.async.wait_group 1;" ::: "memory")

// fast exp on FMA pipe, result scaled by 2^10 (softmax is scale-invariant;
// keeps fp16 P_lo in normal range).
__device__ __forceinline__ float exp_fast_1024(float x) {
    float y = x * 1.44269504088896f;
    float z = y + 12582912.0f;
    int   n = __float_as_int(z) - 0x4B400000;
    float r = z - 12582912.0f;
    float t = y - r;
    float p =            0.00015403530393381609f;
    p = fmaf(p, t, 0.0013333558146428443f);
    p = fmaf(p, t, 0.009618129107628477f);
    p = fmaf(p, t, 0.05550410866482158f);
    p = fmaf(p, t, 0.2402265069591007f);
    p = fmaf(p, t, 0.6931471805599453f);
    p = fmaf(p, t, 1.0f);
    return __int_as_float(__float_as_int(p) + ((n + 10) << 23));
}

// bf16 hi/lo split store (hi = truncate bits, lo = rn remainder)
__device__ __forceinline__ void split_store4(float4 v,
                                             __nv_bfloat16* hp, __nv_bfloat16* lp) {
    uint32_t ax = __float_as_uint(v.x) & 0xFFFF0000u;
    uint32_t ay = __float_as_uint(v.y) & 0xFFFF0000u;
    uint32_t az = __float_as_uint(v.z) & 0xFFFF0000u;
    uint32_t aw = __float_as_uint(v.w) & 0xFFFF0000u;
    float lx = v.x - __uint_as_float(ax);
    float ly = v.y - __uint_as_float(ay);
    float lz = v.z - __uint_as_float(az);
    float lw = v.w - __uint_as_float(aw);
    uint2 h;
    h.x = __byte_perm(ax, ay, 0x7632);
    h.y = __byte_perm(az, aw, 0x7632);
    *(uint2*)hp = h;
    __nv_bfloat162 l01 = __float22bfloat162_rn(make_float2(lx, ly));
    __nv_bfloat162 l23 = __float22bfloat162_rn(make_float2(lz, lw));
    uint2 l;
    l.x = *(uint32_t*)&l01;
    l.y = *(uint32_t*)&l23;
    *(uint2*)lp = l;
}

// fp16 hi/lo split store
__device__ __forceinline__ void split_store4_f16(float4 v, __half* hp, __half* lp) {
    __half h0 = __float2half_rn(v.x);
    __half h1 = __float2half_rn(v.y);
    __half h2 = __float2half_rn(v.z);
    __half h3 = __float2half_rn(v.w);
    __half2 hh01 = __halves2half2(h0, h1);
    __half2 hh23 = __halves2half2(h2, h3);
    uint2 h;
    h.x = *(uint32_t*)&hh01;
    h.y = *(uint32_t*)&hh23;
    *(uint2*)hp = h;
    __half2 ll01 = __floats2half2_rn(v.x - __half2float(h0), v.y - __half2float(h1));
    __half2 ll23 = __floats2half2_rn(v.z - __half2float(h2), v.w - __half2float(h3));
    uint2 l;
    l.x = *(uint32_t*)&ll01;
    l.y = *(uint32_t*)&ll23;
    *(uint2*)lp = l;
}

// ---------------------------------------------------------------------------
// conversion kernels
// ---------------------------------------------------------------------------
__global__ __launch_bounds__(256) void split_bf16_kernel(
    const float* __restrict__ src,
    __nv_bfloat16* __restrict__ hi, __nv_bfloat16* __restrict__ lo, int n4)
{
    int i = blockIdx.x * blockDim.x + threadIdx.x;
    if (i >= n4) return;
    float4 v = ((const float4*)src)[i];
    split_store4(v, hi + i * 4, lo + i * 4);
}

__global__ __launch_bounds__(256) void tof16_kernel(
    const float* __restrict__ src, __half* __restrict__ dst, int n4)
{
    int i = blockIdx.x * blockDim.x + threadIdx.x;
    if (i >= n4) return;
    float4 v = ((const float4*)src)[i];
    __half2 h01 = __floats2half2_rn(v.x, v.y);
    __half2 h23 = __floats2half2_rn(v.z, v.w);
    uint2 u;
    u.x = *(uint32_t*)&h01;
    u.y = *(uint32_t*)&h23;
    ((uint2*)dst)[i] = u;
}

// ---------------------------------------------------------------------------
// bf16 3-product split NT GEMM (used for V projection and output projection)
// epilogue: fp32 out OR fp16 hi/lo split out
// ---------------------------------------------------------------------------
#define GPITCH 40
#define TILE_E (128 * GPITCH)
#define TILE_B (TILE_E * 2)
#define STAGE_B (4 * TILE_B)
#define GEMM_SMEM (2 * STAGE_B)          // 81920
#define NSTAGE (Dmod / 32)               // 32

__global__ __launch_bounds__(256) void gemm_wmma(
    const __nv_bfloat16* __restrict__ Ahi, const __nv_bfloat16* __restrict__ Alo,
    const __nv_bfloat16* __restrict__ Bhi, const __nv_bfloat16* __restrict__ Blo,
    const float* __restrict__ bias,
    float* __restrict__ Cf,
    __half* __restrict__ outHf, __half* __restrict__ outLf)
{
    extern __shared__ char dsm[];
    const int tid = threadIdx.x;
    const int w = tid >> 5;
    const int lane = tid & 31;
    const int m0 = blockIdx.y * 128;
    const int n0 = blockIdx.x * 128;
    const int wm = w >> 1;
    const int wn = w & 1;

    const uint32_t sb = smem_u32(dsm);
    const int lrow = tid >> 1;
    const int v0 = (tid & 1) * 2;

    const __nv_bfloat16* ah = Ahi + (size_t)(m0 + lrow) * Dmod;
    const __nv_bfloat16* al = Alo + (size_t)(m0 + lrow) * Dmod;
    const __nv_bfloat16* bh = Bhi + (size_t)(n0 + lrow) * Dmod;
    const __nv_bfloat16* bl = Blo + (size_t)(n0 + lrow) * Dmod;

    wmma::fragment<wmma::accumulator, 16, 16, 16, float> acc[2][4];
#pragma unroll
    for (int i = 0; i < 2; i++)
#pragma unroll
        for (int j = 0; j < 4; j++) wmma::fill_fragment(acc[i][j], 0.0f);

    auto load_stage = [&](int c, int s) {
        const int kc0 = c * 32;
        const uint32_t st = sb + s * STAGE_B;
#pragma unroll
        for (int vv = 0; vv < 2; vv++) {
            int v = v0 + vv;
            uint32_t so = (uint32_t)(lrow * (GPITCH * 2) + v * 16);
            cp16(st + 0 * TILE_B + so, ah + kc0 + v * 8);
            cp16(st + 1 * TILE_B + so, al + kc0 + v * 8);
            cp16(st + 2 * TILE_B + so, bh + kc0 + v * 8);
            cp16(st + 3 * TILE_B + so, bl + kc0 + v * 8);
        }
        CP_COMMIT();
    };

    load_stage(0, 0);

    for (int c = 0; c < NSTAGE; c++) {
        const int s = c & 1;
        if (c + 1 < NSTAGE) {
            load_stage(c + 1, s ^ 1);
            CP_WAIT1();
        } else {
            CP_WAIT0();
        }
        __syncthreads();

        const __nv_bfloat16* sAhi = (const __nv_bfloat16*)(dsm + s * STAGE_B);
        const __nv_bfloat16* sAlo = sAhi + TILE_E;
        const __nv_bfloat16* sBhi = sAlo + TILE_E;
        const __nv_bfloat16* sBlo = sBhi + TILE_E;

#pragma unroll
        for (int ks = 0; ks < 2; ks++) {
            wmma::fragment<wmma::matrix_a, 16, 16, 16, __nv_bfloat16, wmma::row_major> afh[2], afl[2];
            wmma::fragment<wmma::matrix_b, 16, 16, 16, __nv_bfloat16, wmma::col_major> bfh[4], bfl[4];
#pragma unroll
            for (int i = 0; i < 2; i++) {
                wmma::load_matrix_sync(afh[i], sAhi + (wm * 32 + i * 16) * GPITCH + ks * 16, GPITCH);
                wmma::load_matrix_sync(afl[i], sAlo + (wm * 32 + i * 16) * GPITCH + ks * 16, GPITCH);
            }
#pragma unroll
            for (int j = 0; j < 4; j++) {
                wmma::load_matrix_sync(bfh[j], sBhi + (wn * 64 + j * 16) * GPITCH + ks * 16, GPITCH);
                wmma::load_matrix_sync(bfl[j], sBlo + (wn * 64 + j * 16) * GPITCH + ks * 16, GPITCH);
            }
#pragma unroll
            for (int i = 0; i < 2; i++)
#pragma unroll
                for (int j = 0; j < 4; j++) {
                    wmma::mma_sync(acc[i][j], afh[i], bfh[j], acc[i][j]);
                    wmma::mma_sync(acc[i][j], afh[i], bfl[j], acc[i][j]);
                    wmma::mma_sync(acc[i][j], afl[i], bfh[j], acc[i][j]);
                }
        }
        __syncthreads();
    }

    float* ep = (float*)dsm + w * (32 * 68);
#pragma unroll
    for (int i = 0; i < 2; i++)
#pragma unroll
        for (int j = 0; j < 4; j++)
            wmma::store_matrix_sync(ep + i * 16 * 68 + j * 16, acc[i][j], 68, wmma::mem_row_major);
    __syncwarp();

    const float* brow = bias + n0 + wn * 64;
    const size_t rowbase = (size_t)(m0 + wm * 32 + lane) * Dmod + n0 + wn * 64;

    if (Cf != nullptr) {
        float* crow = Cf + rowbase;
#pragma unroll
        for (int cc = 0; cc < 64; cc += 4) {
            float4 vv = *(const float4*)(ep + lane * 68 + cc);
            vv.x += brow[cc + 0];
            vv.y += brow[cc + 1];
            vv.z += brow[cc + 2];
            vv.w += brow[cc + 3];
            *(float4*)(crow + cc) = vv;
        }
    } else {
#pragma unroll
        for (int cc = 0; cc < 64; cc += 4) {
            float4 vv = *(const float4*)(ep + lane * 68 + cc);
            vv.x += brow[cc + 0];
            vv.y += brow[cc + 1];
            vv.z += brow[cc + 2];
            vv.w += brow[cc + 3];
            split_store4_f16(vv, outHf + rowbase + cc, outLf + rowbase + cc);
        }
    }
}

// ---------------------------------------------------------------------------
// fp16 single-product NT GEMM (Q and K projections): C = A @ B^T + bias, fp16 out
// ---------------------------------------------------------------------------
#define F16_TILE_E (128 * GPITCH)
#define F16_TILE_B (F16_TILE_E * 2)       // 10240
#define F16_STAGE_B (2 * F16_TILE_B)      // 20480
#define F16_GEMM_SMEM 69632               // max(2*STAGE, epilogue 8*32*68*4)

__global__ __launch_bounds__(256) void gemm_f16(
    const __half* __restrict__ A, const __half* __restrict__ B,
    const float* __restrict__ bias, __half* __restrict__ C, float oscale)
{
    extern __shared__ char dsm[];
    const int tid = threadIdx.x;
    const int w = tid >> 5;
    const int lane = tid & 31;
    const int m0 = blockIdx.y * 128;
    const int n0 = blockIdx.x * 128;
    const int wm = w >> 1;
    const int wn = w & 1;

    const uint32_t sb = smem_u32(dsm);
    const int lrow = tid >> 1;
    const int v0 = (tid & 1) * 2;

    const __half* ag = A + (size_t)(m0 + lrow) * Dmod;
    const __half* bg = B + (size_t)(n0 + lrow) * Dmod;

    wmma::fragment<wmma::accumulator, 16, 16, 16, float> acc[2][4];
#pragma unroll
    for (int i = 0; i < 2; i++)
#pragma unroll
        for (int j = 0; j < 4; j++) wmma::fill_fragment(acc[i][j], 0.0f);

    auto load_stage = [&](int c, int s) {
        const int kc0 = c * 32;
        const uint32_t st = sb + s * F16_STAGE_B;
#pragma unroll
        for (int vv = 0; vv < 2; vv++) {
            int v = v0 + vv;
            uint32_t so = (uint32_t)(lrow * (GPITCH * 2) + v * 16);
            cp16(st + so, ag + kc0 + v * 8);
            cp16(st + F16_TILE_B + so, bg + kc0 + v * 8);
        }
        CP_COMMIT();
    };

    load_stage(0, 0);

    for (int c = 0; c < NSTAGE; c++) {
        const int s = c & 1;
        if (c + 1 < NSTAGE) {
            load_stage(c + 1, s ^ 1);
            CP_WAIT1();
        } else {
            CP_WAIT0();
        }
        __syncthreads();

        const __half* sA = (const __half*)(dsm + s * F16_STAGE_B);
        const __half* sB = sA + F16_TILE_E;

#pragma unroll
        for (int ks = 0; ks < 2; ks++) {
            wmma::fragment<wmma::matrix_a, 16, 16, 16, __half, wmma::row_major> af[2];
            wmma::fragment<wmma::matrix_b, 16, 16, 16, __half, wmma::col_major> bf[4];
#pragma unroll
            for (int i = 0; i < 2; i++)
                wmma::load_matrix_sync(af[i], sA + (wm * 32 + i * 16) * GPITCH + ks * 16, GPITCH);
#pragma unroll
            for (int j = 0; j < 4; j++)
                wmma::load_matrix_sync(bf[j], sB + (wn * 64 + j * 16) * GPITCH + ks * 16, GPITCH);
#pragma unroll
            for (int i = 0; i < 2; i++)
#pragma unroll
                for (int j = 0; j < 4; j++)
                    wmma::mma_sync(acc[i][j], af[i], bf[j], acc[i][j]);
        }
        __syncthreads();
    }

    float* ep = (float*)dsm + w * (32 * 68);
#pragma unroll
    for (int i = 0; i < 2; i++)
#pragma unroll
        for (int j = 0; j < 4; j++)
            wmma::store_matrix_sync(ep + i * 16 * 68 + j * 16, acc[i][j], 68, wmma::mem_row_major);
    __syncwarp();

    const float* brow = bias + n0 + wn * 64;
    __half* crow = C + (size_t)(m0 + wm * 32 + lane) * Dmod + n0 + wn * 64;
#pragma unroll
    for (int cc = 0; cc < 64; cc += 4) {
        float4 vv = *(const float4*)(ep + lane * 68 + cc);
        vv.x = (vv.x + brow[cc + 0]) * oscale;
        vv.y = (vv.y + brow[cc + 1]) * oscale;
        vv.z = (vv.z + brow[cc + 2]) * oscale;
        vv.w = (vv.w + brow[cc + 3]) * oscale;
        __half2 h01 = __floats2half2_rn(vv.x, vv.y);
        __half2 h23 = __floats2half2_rn(vv.z, vv.w);
        uint2 u;
        u.x = *(uint32_t*)&h01;
        u.y = *(uint32_t*)&h23;
        *(uint2*)(crow + cc) = u;
    }
}

// ---------------------------------------------------------------------------
// Attention: S = Qf16 @ Kf16^T (single product), exp (FMA-pipe, x1024 scaled),
// P split fp16 hi/lo, O += P @ (Vh+Vl) (3-product). No max subtraction
// (scores tiny by the 1/32 quirk). Output: bf16 hi/lo, [B,H,N,Dh] contiguous.
// K/V double buffered.
// ---------------------------------------------------------------------------
#define QT 64
#define KTILE 64
#define APITCH 72
#define SPITCH 68
#define TB2 (64 * APITCH * 2)       // 9216 bytes per fp16 tile
#define SM_QF 0
#define SM_KF(s)  ((1 + (s)) * TB2)
#define SM_VH(s)  ((3 + (s)) * TB2)
#define SM_VL(s)  ((5 + (s)) * TB2)
#define SM_PH (7 * TB2)
#define SM_PL (8 * TB2)
#define SM_S  (9 * TB2)
#define ATTN_SMEM (9 * TB2 + 64 * SPITCH * 4)   // 100352

__global__ __launch_bounds__(128) void attn_tc_kernel()
{
    extern __shared__ char asm_[];
    const uint32_t sb = smem_u32(asm_);
    const int tid = threadIdx.x;
    const int w = tid >> 5;
    const int lane = tid & 31;
    const int bh = blockIdx.y;
    const int b = bh / Hh;
    const int h = bh % Hh;
    const int qRow0 = blockIdx.x * QT;

    const size_t headoff = (size_t)h * Dhd;
    const __half* q_g  = g_qf  + ((size_t)b * Nseq + qRow0) * Dmod + headoff;
    const __half* k_g  = g_kf  + (size_t)b * Nseq * Dmod + headoff;
    const __half* vh_g = g_vhf + (size_t)b * Nseq * Dmod + headoff;
    const __half* vl_g = g_vlf + (size_t)b * Nseq * Dmod + headoff;

    auto load_tile = [&](uint32_t dst, const __half* g) {
#pragma unroll
        for (int t = 0; t < 4; t++) {
            int id = tid + t * 128;
            int row = id >> 3;
            int c8 = (id & 7) * 8;
            cp16(dst + (uint32_t)(row * APITCH + c8) * 2, g + (size_t)row * Dmod + c8);
        }
    };

    load_tile(sb + SM_QF, q_g);
    load_tile(sb + SM_KF(0), k_g);
    load_tile(sb + SM_VH(0), vh_g);
    load_tile(sb + SM_VL(0), vl_g);
    CP_COMMIT();
    CP_WAIT0();
    __syncthreads();

    // hoist Q fragments (warp strip rows [16w,16w+16))
    wmma::fragment<wmma::matrix_a, 16, 16, 16, __half, wmma::row_major> qf[4];
    {
        const __half* Qf = (const __half*)(asm_ + SM_QF) + w * 16 * APITCH;
#pragma unroll
        for (int ks = 0; ks < 4; ks++)
            wmma::load_matrix_sync(qf[ks], Qf + ks * 16, APITCH);
    }

    wmma::fragment<wmma::accumulator, 16, 16, 16, float> oacc[4];
#pragma unroll
    for (int dt = 0; dt < 4; dt++) wmma::fill_fragment(oacc[dt], 0.0f);

    const int rl = lane >> 1;
    const int c0 = (lane & 1) * 32;
    float lsum = 0.0f;

    float* Srow = (float*)(asm_ + SM_S) + (w * 16 + rl) * SPITCH + c0;
    __half* Ph_row = (__half*)(asm_ + SM_PH) + (w * 16 + rl) * APITCH + c0;
    __half* Pl_row = (__half*)(asm_ + SM_PL) + (w * 16 + rl) * APITCH + c0;

    const int NT = Nseq / KTILE;
    for (int kt = 0; kt < NT; kt++) {
        const int s = kt & 1;
        // prefetch next K/V into other buffer
        if (kt + 1 < NT) {
            const size_t koff = (size_t)(kt + 1) * KTILE * Dmod;
            load_tile(sb + SM_KF(s ^ 1), k_g + koff);
            load_tile(sb + SM_VH(s ^ 1), vh_g + koff);
            load_tile(sb + SM_VL(s ^ 1), vl_g + koff);
            CP_COMMIT();
        }

        // ---- S = Q @ K^T (single product, warp-private 16x64 strip) ----
        const __half* Kf = (const __half*)(asm_ + SM_KF(s));
        float* Sst = (float*)(asm_ + SM_S) + (w * 16) * SPITCH;
#pragma unroll
        for (int jt = 0; jt < 4; jt++) {
            wmma::fragment<wmma::accumulator, 16, 16, 16, float> sacc;
            wmma::fill_fragment(sacc, 0.0f);
#pragma unroll
            for (int ks = 0; ks < 4; ks++) {
                wmma::fragment<wmma::matrix_b, 16, 16, 16, __half, wmma::col_major> kf;
                wmma::load_matrix_sync(kf, Kf + (jt * 16) * APITCH + ks * 16, APITCH);
                wmma::mma_sync(sacc, qf[ks], kf, sacc);
            }
            wmma::store_matrix_sync(Sst + jt * 16, sacc, SPITCH, wmma::mem_row_major);
        }
        __syncwarp();

        // ---- exp (x1024) + row-sum + P fp16 hi/lo split ----
#pragma unroll
        for (int cc = 0; cc < 32; cc += 4) {
            float4 s4 = *(const float4*)(Srow + cc);
            float4 e4;
            e4.x = exp_fast_1024(s4.x);
            e4.y = exp_fast_1024(s4.y);
            e4.z = exp_fast_1024(s4.z);
            e4.w = exp_fast_1024(s4.w);
            lsum += (e4.x + e4.y) + (e4.z + e4.w);
            split_store4_f16(e4, Ph_row + cc, Pl_row + cc);
        }
        __syncwarp();

        // ---- O += P @ V (3-product) ----
        const __half* Ph = (const __half*)(asm_ + SM_PH) + w * 16 * APITCH;
        const __half* Pl = (const __half*)(asm_ + SM_PL) + w * 16 * APITCH;
        const __half* Vh = (const __half*)(asm_ + SM_VH(s));
        const __half* Vl = (const __half*)(asm_ + SM_VL(s));
#pragma unroll
        for (int kk = 0; kk < 4; kk++) {
            wmma::fragment<wmma::matrix_a, 16, 16, 16, __half, wmma::row_major> pfh, pfl;
            wmma::load_matrix_sync(pfh, Ph + kk * 16, APITCH);
            wmma::load_matrix_sync(pfl, Pl + kk * 16, APITCH);
#pragma unroll
            for (int dt = 0; dt < 4; dt++) {
                wmma::fragment<wmma::matrix_b, 16, 16, 16, __half, wmma::row_major> vfh, vfl;
                wmma::load_matrix_sync(vfh, Vh + (kk * 16) * APITCH + dt * 16, APITCH);
                wmma::load_matrix_sync(vfl, Vl + (kk * 16) * APITCH + dt * 16, APITCH);
                wmma::mma_sync(oacc[dt], pfh, vfh, oacc[dt]);
                wmma::mma_sync(oacc[dt], pfh, vfl, oacc[dt]);
                wmma::mma_sync(oacc[dt], pfl, vfh, oacc[dt]);
            }
        }

        if (kt + 1 < NT) CP_WAIT0();
        __syncthreads();
    }

    // ---- epilogue ----
    {
        float* Ost = (float*)(asm_ + SM_S) + (w * 16) * SPITCH;
#pragma unroll
        for (int dt = 0; dt < 4; dt++)
            wmma::store_matrix_sync(Ost + dt * 16, oacc[dt], SPITCH, wmma::mem_row_major);
    }
    __syncwarp();

    float ltot = lsum + __shfl_xor_sync(0xffffffffu, lsum, 1);
    float inv = 1.0f / ltot;

    const int n = qRow0 + w * 16 + rl;
    const size_t obase = (((size_t)bh * Nseq) + n) * Dhd + c0;
    const float* Orow = (float*)(asm_ + SM_S) + (w * 16 + rl) * SPITCH + c0;
#pragma unroll
    for (int cc = 0; cc < 32; cc += 4) {
        float4 v4 = *(const float4*)(Orow + cc);
        v4.x *= inv; v4.y *= inv; v4.z *= inv; v4.w *= inv;
        split_store4(v4, g_ohi + obase + cc, g_olo + obase + cc);
    }
}

// ---------------------------------------------------------------------------
extern "C" void kernel_launch(void* const* d_in, const int* in_sizes, int n_in,
                              void* d_out, int out_size)
{
    const float* x  = (const float*)d_in[0];
    const float* Wq = (const float*)d_in[1];
    const float* bq = (const float*)d_in[2];
    const float* Wk = (const float*)d_in[3];
    const float* bk = (const float*)d_in[4];
    const float* Wv = (const float*)d_in[5];
    const float* bv = (const float*)d_in[6];
    const float* Wc = (const float*)d_in[7];
    const float* bc = (const float*)d_in[8];
    float* out = (float*)d_out;

    __half *qf, *kf, *vhf, *vlf, *xf, *wqf, *wkf;
    __nv_bfloat16 *xhi, *xlo, *ohi, *olo, *wvhi, *wvlo, *wchi, *wclo;
    cudaGetSymbolAddress((void**)&qf, g_qf);
    cudaGetSymbolAddress((void**)&kf, g_kf);
    cudaGetSymbolAddress((void**)&vhf, g_vhf);
    cudaGetSymbolAddress((void**)&vlf, g_vlf);
    cudaGetSymbolAddress((void**)&xf, g_xf);
    cudaGetSymbolAddress((void**)&wqf, g_wqf);
    cudaGetSymbolAddress((void**)&wkf, g_wkf);
    cudaGetSymbolAddress((void**)&xhi, g_xhi);
    cudaGetSymbolAddress((void**)&xlo, g_xlo);
    cudaGetSymbolAddress((void**)&ohi, g_ohi);
    cudaGetSymbolAddress((void**)&olo, g_olo);
    cudaGetSymbolAddress((void**)&wvhi, g_wvhi);
    cudaGetSymbolAddress((void**)&wvlo, g_wvlo);
    cudaGetSymbolAddress((void**)&wchi, g_wchi);
    cudaGetSymbolAddress((void**)&wclo, g_wclo);

    static bool attr_set = false;
    if (!attr_set) {
        cudaFuncSetAttribute(attn_tc_kernel,
                             cudaFuncAttributeMaxDynamicSharedMemorySize, ATTN_SMEM);
        cudaFuncSetAttribute(gemm_wmma,
                             cudaFuncAttributeMaxDynamicSharedMemorySize, GEMM_SMEM);
        cudaFuncSetAttribute(gemm_f16,
                             cudaFuncAttributeMaxDynamicSharedMemorySize, F16_GEMM_SMEM);
        attr_set = true;
    }

    const int n4x = Mtot * Dmod / 4;
    const int n4w = Dmod * Dmod / 4;
    split_bf16_kernel<<<n4x / 256, 256>>>(x,  xhi, xlo, n4x);
    tof16_kernel<<<n4x / 256, 256>>>(x, xf, n4x);
    tof16_kernel<<<n4w / 256, 256>>>(Wq, wqf, n4w);
    tof16_kernel<<<n4w / 256, 256>>>(Wk, wkf, n4w);
    split_bf16_kernel<<<n4w / 256, 256>>>(Wv, wvhi, wvlo, n4w);
    split_bf16_kernel<<<n4w / 256, 256>>>(Wc, wchi, wclo, n4w);

    dim3 gemm_grid(Dmod / 128, Mtot / 128);  // (8, 32)
    gemm_f16<<<gemm_grid, 256, F16_GEMM_SMEM>>>(xf, wqf, bq, qf, SCALE);
    gemm_f16<<<gemm_grid, 256, F16_GEMM_SMEM>>>(xf, wkf, bk, kf, 1.0f);
    gemm_wmma<<<gemm_grid, 256, GEMM_SMEM>>>(xhi, xlo, wvhi, wvlo, bv,
                                             nullptr, vhf, vlf);

    dim3 attn_grid(Nseq / QT, Bsz * Hh);     // (16, 64)
    attn_tc_kernel<<<attn_grid, 128, ATTN_SMEM>>>();

    gemm_wmma<<<gemm_grid, 256, GEMM_SMEM>>>(ohi, olo, wchi, wclo, bc,
                                             out, nullptr, nullptr);
}

// round 6
// speedup vs baseline: 2.9666x; 1.0508x over previous
#include <cuda_runtime.h>
#include <cuda_bf16.h>
#include <cuda_fp16.h>
#include <mma.h>
#include <math.h>
#include <stdint.h>

using namespace nvcuda;

#define Bsz 4
#define Nseq 1024
#define Dmod 1024
#define Hh 16
#define Dhd 64
#define Mtot (Bsz * Nseq)   // 4096
#define SCALE 0.03125f      // N^-0.5 = 1/32 (faithful quirk)

// ---------------------------------------------------------------------------
// Scratch (allocation-free rule: __device__ globals)
// ---------------------------------------------------------------------------
__device__ __half g_qf[Mtot * Dmod];      // fp16 q (pre-scaled by 1/32)
__device__ __half g_kf[Mtot * Dmod];      // fp16 k
__device__ __half g_vhf[Mtot * Dmod];     // fp16 v hi
__device__ __half g_vlf[Mtot * Dmod];     // fp16 v lo
__device__ __half g_xhf[Mtot * Dmod];     // fp16 x hi
__device__ __half g_xlf[Mtot * Dmod];     // fp16 x lo
__device__ __half g_wqf[Dmod * Dmod];
__device__ __half g_wkf[Dmod * Dmod];
__device__ __half g_wvf[Dmod * Dmod];

__device__ __nv_bfloat16 g_ohi[Mtot * Dmod];
__device__ __nv_bfloat16 g_olo[Mtot * Dmod];
__device__ __nv_bfloat16 g_wchi[Dmod * Dmod];
__device__ __nv_bfloat16 g_wclo[Dmod * Dmod];

// ---------------------------------------------------------------------------
// helpers
// ---------------------------------------------------------------------------
__device__ __forceinline__ uint32_t smem_u32(const void* p) {
    uint32_t a;
    asm("{ .reg .u64 t; cvta.to.shared.u64 t, %1; cvt.u32.u64 %0, t; }"
        : "=r"(a) : "l"(p));
    return a;
}
__device__ __forceinline__ void cp16(uint32_t saddr, const void* g) {
    asm volatile("cp.async.cg.shared.global [%0], [%1], 16;" :: "r"(saddr), "l"(g));
}
#define CP_COMMIT() asm volatile("cp.async.commit_group;" ::: "memory")
#define CP_WAIT0()  asm volatile("cp.async.wait_group 0;" ::: "memory")
#define CP_WAIT1()  asm volatile("cp.async.wait_group 1;" ::: "memory")

// fast exp on FMA pipe, result scaled by 2^10
__device__ __forceinline__ float exp_fast_1024(float x) {
    float y = x * 1.44269504088896f;
    float z = y + 12582912.0f;
    int   n = __float_as_int(z) - 0x4B400000;
    float r = z - 12582912.0f;
    float t = y - r;
    float p =            0.00015403530393381609f;
    p = fmaf(p, t, 0.0013333558146428443f);
    p = fmaf(p, t, 0.009618129107628477f);
    p = fmaf(p, t, 0.05550410866482158f);
    p = fmaf(p, t, 0.2402265069591007f);
    p = fmaf(p, t, 0.6931471805599453f);
    p = fmaf(p, t, 1.0f);
    return __int_as_float(__float_as_int(p) + ((n + 10) << 23));
}

// bf16 hi/lo split store
__device__ __forceinline__ void split_store4(float4 v,
                                             __nv_bfloat16* hp, __nv_bfloat16* lp) {
    uint32_t ax = __float_as_uint(v.x) & 0xFFFF0000u;
    uint32_t ay = __float_as_uint(v.y) & 0xFFFF0000u;
    uint32_t az = __float_as_uint(v.z) & 0xFFFF0000u;
    uint32_t aw = __float_as_uint(v.w) & 0xFFFF0000u;
    float lx = v.x - __uint_as_float(ax);
    float ly = v.y - __uint_as_float(ay);
    float lz = v.z - __uint_as_float(az);
    float lw = v.w - __uint_as_float(aw);
    uint2 h;
    h.x = __byte_perm(ax, ay, 0x7632);
    h.y = __byte_perm(az, aw, 0x7632);
    *(uint2*)hp = h;
    __nv_bfloat162 l01 = __float22bfloat162_rn(make_float2(lx, ly));
    __nv_bfloat162 l23 = __float22bfloat162_rn(make_float2(lz, lw));
    uint2 l;
    l.x = *(uint32_t*)&l01;
    l.y = *(uint32_t*)&l23;
    *(uint2*)lp = l;
}

// fp16 hi/lo split store
__device__ __forceinline__ void split_store4_f16(float4 v, __half* hp, __half* lp) {
    __half h0 = __float2half_rn(v.x);
    __half h1 = __float2half_rn(v.y);
    __half h2 = __float2half_rn(v.z);
    __half h3 = __float2half_rn(v.w);
    __half2 hh01 = __halves2half2(h0, h1);
    __half2 hh23 = __halves2half2(h2, h3);
    uint2 h;
    h.x = *(uint32_t*)&hh01;
    h.y = *(uint32_t*)&hh23;
    *(uint2*)hp = h;
    __half2 ll01 = __floats2half2_rn(v.x - __half2float(h0), v.y - __half2float(h1));
    __half2 ll23 = __floats2half2_rn(v.z - __half2float(h2), v.w - __half2float(h3));
    uint2 l;
    l.x = *(uint32_t*)&ll01;
    l.y = *(uint32_t*)&ll23;
    *(uint2*)lp = l;
}

// ---------------------------------------------------------------------------
// conversion kernels
// ---------------------------------------------------------------------------
__global__ __launch_bounds__(256) void split_bf16_kernel(
    const float* __restrict__ src,
    __nv_bfloat16* __restrict__ hi, __nv_bfloat16* __restrict__ lo, int n4)
{
    int i = blockIdx.x * blockDim.x + threadIdx.x;
    if (i >= n4) return;
    float4 v = ((const float4*)src)[i];
    split_store4(v, hi + i * 4, lo + i * 4);
}

__global__ __launch_bounds__(256) void split_f16_kernel(
    const float* __restrict__ src,
    __half* __restrict__ hi, __half* __restrict__ lo, int n4)
{
    int i = blockIdx.x * blockDim.x + threadIdx.x;
    if (i >= n4) return;
    float4 v = ((const float4*)src)[i];
    split_store4_f16(v, hi + i * 4, lo + i * 4);
}

__global__ __launch_bounds__(256) void tof16_kernel(
    const float* __restrict__ src, __half* __restrict__ dst, int n4)
{
    int i = blockIdx.x * blockDim.x + threadIdx.x;
    if (i >= n4) return;
    float4 v = ((const float4*)src)[i];
    __half2 h01 = __floats2half2_rn(v.x, v.y);
    __half2 h23 = __floats2half2_rn(v.z, v.w);
    uint2 u;
    u.x = *(uint32_t*)&h01;
    u.y = *(uint32_t*)&h23;
    ((uint2*)dst)[i] = u;
}

// ---------------------------------------------------------------------------
// common GEMM tile constants
// ---------------------------------------------------------------------------
#define GPITCH 40
#define TILE_E (128 * GPITCH)
#define TILE_B (TILE_E * 2)              // 10240 bytes
#define NSTAGE (Dmod / 32)               // 32

// ---------------------------------------------------------------------------
// bf16 3-product split NT GEMM (output projection): fp32 out + bias
// ---------------------------------------------------------------------------
#define BF3_STAGE_B (4 * TILE_B)
#define BF3_SMEM (2 * BF3_STAGE_B)       // 81920

__global__ __launch_bounds__(256) void gemm_wmma(
    const __nv_bfloat16* __restrict__ Ahi, const __nv_bfloat16* __restrict__ Alo,
    const __nv_bfloat16* __restrict__ Bhi, const __nv_bfloat16* __restrict__ Blo,
    const float* __restrict__ bias, float* __restrict__ Cf)
{
    extern __shared__ char dsm[];
    const int tid = threadIdx.x;
    const int w = tid >> 5;
    const int lane = tid & 31;
    const int m0 = blockIdx.y * 128;
    const int n0 = blockIdx.x * 128;
    const int wm = w >> 1;
    const int wn = w & 1;

    const uint32_t sb = smem_u32(dsm);
    const int lrow = tid >> 1;
    const int v0 = (tid & 1) * 2;

    const __nv_bfloat16* ah = Ahi + (size_t)(m0 + lrow) * Dmod;
    const __nv_bfloat16* al = Alo + (size_t)(m0 + lrow) * Dmod;
    const __nv_bfloat16* bh = Bhi + (size_t)(n0 + lrow) * Dmod;
    const __nv_bfloat16* bl = Blo + (size_t)(n0 + lrow) * Dmod;

    wmma::fragment<wmma::accumulator, 16, 16, 16, float> acc[2][4];
#pragma unroll
    for (int i = 0; i < 2; i++)
#pragma unroll
        for (int j = 0; j < 4; j++) wmma::fill_fragment(acc[i][j], 0.0f);

    auto load_stage = [&](int c, int s) {
        const int kc0 = c * 32;
        const uint32_t st = sb + s * BF3_STAGE_B;
#pragma unroll
        for (int vv = 0; vv < 2; vv++) {
            int v = v0 + vv;
            uint32_t so = (uint32_t)(lrow * (GPITCH * 2) + v * 16);
            cp16(st + 0 * TILE_B + so, ah + kc0 + v * 8);
            cp16(st + 1 * TILE_B + so, al + kc0 + v * 8);
            cp16(st + 2 * TILE_B + so, bh + kc0 + v * 8);
            cp16(st + 3 * TILE_B + so, bl + kc0 + v * 8);
        }
        CP_COMMIT();
    };

    load_stage(0, 0);

    for (int c = 0; c < NSTAGE; c++) {
        const int s = c & 1;
        if (c + 1 < NSTAGE) {
            load_stage(c + 1, s ^ 1);
            CP_WAIT1();
        } else {
            CP_WAIT0();
        }
        __syncthreads();

        const __nv_bfloat16* sAhi = (const __nv_bfloat16*)(dsm + s * BF3_STAGE_B);
        const __nv_bfloat16* sAlo = sAhi + TILE_E;
        const __nv_bfloat16* sBhi = sAlo + TILE_E;
        const __nv_bfloat16* sBlo = sBhi + TILE_E;

#pragma unroll
        for (int ks = 0; ks < 2; ks++) {
            wmma::fragment<wmma::matrix_a, 16, 16, 16, __nv_bfloat16, wmma::row_major> afh[2], afl[2];
            wmma::fragment<wmma::matrix_b, 16, 16, 16, __nv_bfloat16, wmma::col_major> bfh[4], bfl[4];
#pragma unroll
            for (int i = 0; i < 2; i++) {
                wmma::load_matrix_sync(afh[i], sAhi + (wm * 32 + i * 16) * GPITCH + ks * 16, GPITCH);
                wmma::load_matrix_sync(afl[i], sAlo + (wm * 32 + i * 16) * GPITCH + ks * 16, GPITCH);
            }
#pragma unroll
            for (int j = 0; j < 4; j++) {
                wmma::load_matrix_sync(bfh[j], sBhi + (wn * 64 + j * 16) * GPITCH + ks * 16, GPITCH);
                wmma::load_matrix_sync(bfl[j], sBlo + (wn * 64 + j * 16) * GPITCH + ks * 16, GPITCH);
            }
#pragma unroll
            for (int i = 0; i < 2; i++)
#pragma unroll
                for (int j = 0; j < 4; j++) {
                    wmma::mma_sync(acc[i][j], afh[i], bfh[j], acc[i][j]);
                    wmma::mma_sync(acc[i][j], afh[i], bfl[j], acc[i][j]);
                    wmma::mma_sync(acc[i][j], afl[i], bfh[j], acc[i][j]);
                }
        }
        __syncthreads();
    }

    float* ep = (float*)dsm + w * (32 * 68);
#pragma unroll
    for (int i = 0; i < 2; i++)
#pragma unroll
        for (int j = 0; j < 4; j++)
            wmma::store_matrix_sync(ep + i * 16 * 68 + j * 16, acc[i][j], 68, wmma::mem_row_major);
    __syncwarp();

    const float* brow = bias + n0 + wn * 64;
    float* crow = Cf + (size_t)(m0 + wm * 32 + lane) * Dmod + n0 + wn * 64;
#pragma unroll
    for (int cc = 0; cc < 64; cc += 4) {
        float4 vv = *(const float4*)(ep + lane * 68 + cc);
        vv.x += brow[cc + 0];
        vv.y += brow[cc + 1];
        vv.z += brow[cc + 2];
        vv.w += brow[cc + 3];
        *(float4*)(crow + cc) = vv;
    }
}

// ---------------------------------------------------------------------------
// fp16 single-product NT GEMM (Q/K projections): fp16 out, scaled
// ---------------------------------------------------------------------------
#define F16_STAGE_B (2 * TILE_B)          // 20480
#define F16_SMEM 69632

__global__ __launch_bounds__(256) void gemm_f16(
    const __half* __restrict__ A, const __half* __restrict__ B,
    const float* __restrict__ bias, __half* __restrict__ C, float oscale)
{
    extern __shared__ char dsm[];
    const int tid = threadIdx.x;
    const int w = tid >> 5;
    const int lane = tid & 31;
    const int m0 = blockIdx.y * 128;
    const int n0 = blockIdx.x * 128;
    const int wm = w >> 1;
    const int wn = w & 1;

    const uint32_t sb = smem_u32(dsm);
    const int lrow = tid >> 1;
    const int v0 = (tid & 1) * 2;

    const __half* ag = A + (size_t)(m0 + lrow) * Dmod;
    const __half* bg = B + (size_t)(n0 + lrow) * Dmod;

    wmma::fragment<wmma::accumulator, 16, 16, 16, float> acc[2][4];
#pragma unroll
    for (int i = 0; i < 2; i++)
#pragma unroll
        for (int j = 0; j < 4; j++) wmma::fill_fragment(acc[i][j], 0.0f);

    auto load_stage = [&](int c, int s) {
        const int kc0 = c * 32;
        const uint32_t st = sb + s * F16_STAGE_B;
#pragma unroll
        for (int vv = 0; vv < 2; vv++) {
            int v = v0 + vv;
            uint32_t so = (uint32_t)(lrow * (GPITCH * 2) + v * 16);
            cp16(st + so, ag + kc0 + v * 8);
            cp16(st + TILE_B + so, bg + kc0 + v * 8);
        }
        CP_COMMIT();
    };

    load_stage(0, 0);

    for (int c = 0; c < NSTAGE; c++) {
        const int s = c & 1;
        if (c + 1 < NSTAGE) {
            load_stage(c + 1, s ^ 1);
            CP_WAIT1();
        } else {
            CP_WAIT0();
        }
        __syncthreads();

        const __half* sA = (const __half*)(dsm + s * F16_STAGE_B);
        const __half* sB = sA + TILE_E;

#pragma unroll
        for (int ks = 0; ks < 2; ks++) {
            wmma::fragment<wmma::matrix_a, 16, 16, 16, __half, wmma::row_major> af[2];
            wmma::fragment<wmma::matrix_b, 16, 16, 16, __half, wmma::col_major> bf[4];
#pragma unroll
            for (int i = 0; i < 2; i++)
                wmma::load_matrix_sync(af[i], sA + (wm * 32 + i * 16) * GPITCH + ks * 16, GPITCH);
#pragma unroll
            for (int j = 0; j < 4; j++)
                wmma::load_matrix_sync(bf[j], sB + (wn * 64 + j * 16) * GPITCH + ks * 16, GPITCH);
#pragma unroll
            for (int i = 0; i < 2; i++)
#pragma unroll
                for (int j = 0; j < 4; j++)
                    wmma::mma_sync(acc[i][j], af[i], bf[j], acc[i][j]);
        }
        __syncthreads();
    }

    float* ep = (float*)dsm + w * (32 * 68);
#pragma unroll
    for (int i = 0; i < 2; i++)
#pragma unroll
        for (int j = 0; j < 4; j++)
            wmma::store_matrix_sync(ep + i * 16 * 68 + j * 16, acc[i][j], 68, wmma::mem_row_major);
    __syncwarp();

    const float* brow = bias + n0 + wn * 64;
    __half* crow = C + (size_t)(m0 + wm * 32 + lane) * Dmod + n0 + wn * 64;
#pragma unroll
    for (int cc = 0; cc < 64; cc += 4) {
        float4 vv = *(const float4*)(ep + lane * 68 + cc);
        vv.x = (vv.x + brow[cc + 0]) * oscale;
        vv.y = (vv.y + brow[cc + 1]) * oscale;
        vv.z = (vv.z + brow[cc + 2]) * oscale;
        vv.w = (vv.w + brow[cc + 3]) * oscale;
        __half2 h01 = __floats2half2_rn(vv.x, vv.y);
        __half2 h23 = __floats2half2_rn(vv.z, vv.w);
        uint2 u;
        u.x = *(uint32_t*)&h01;
        u.y = *(uint32_t*)&h23;
        *(uint2*)(crow + cc) = u;
    }
}

// ---------------------------------------------------------------------------
// fp16 2-product NT GEMM (V projection): C = (Ahi+Alo) @ B^T + bias,
// fp16 hi/lo split output.
// ---------------------------------------------------------------------------
#define P2_STAGE_B (3 * TILE_B)           // 30720
#define P2_SMEM 69632                     // max(2*30720=61440, epilogue 69632)

__global__ __launch_bounds__(256) void gemm_f16_2p(
    const __half* __restrict__ Ahi, const __half* __restrict__ Alo,
    const __half* __restrict__ B,
    const float* __restrict__ bias,
    __half* __restrict__ outH, __half* __restrict__ outL)
{
    extern __shared__ char dsm[];
    const int tid = threadIdx.x;
    const int w = tid >> 5;
    const int lane = tid & 31;
    const int m0 = blockIdx.y * 128;
    const int n0 = blockIdx.x * 128;
    const int wm = w >> 1;
    const int wn = w & 1;

    const uint32_t sb = smem_u32(dsm);
    const int lrow = tid >> 1;
    const int v0 = (tid & 1) * 2;

    const __half* ah = Ahi + (size_t)(m0 + lrow) * Dmod;
    const __half* al = Alo + (size_t)(m0 + lrow) * Dmod;
    const __half* bg = B   + (size_t)(n0 + lrow) * Dmod;

    wmma::fragment<wmma::accumulator, 16, 16, 16, float> acc[2][4];
#pragma unroll
    for (int i = 0; i < 2; i++)
#pragma unroll
        for (int j = 0; j < 4; j++) wmma::fill_fragment(acc[i][j], 0.0f);

    auto load_stage = [&](int c, int s) {
        const int kc0 = c * 32;
        const uint32_t st = sb + s * P2_STAGE_B;
#pragma unroll
        for (int vv = 0; vv < 2; vv++) {
            int v = v0 + vv;
            uint32_t so = (uint32_t)(lrow * (GPITCH * 2) + v * 16);
            cp16(st + 0 * TILE_B + so, ah + kc0 + v * 8);
            cp16(st + 1 * TILE_B + so, al + kc0 + v * 8);
            cp16(st + 2 * TILE_B + so, bg + kc0 + v * 8);
        }
        CP_COMMIT();
    };

    load_stage(0, 0);

    for (int c = 0; c < NSTAGE; c++) {
        const int s = c & 1;
        if (c + 1 < NSTAGE) {
            load_stage(c + 1, s ^ 1);
            CP_WAIT1();
        } else {
            CP_WAIT0();
        }
        __syncthreads();

        const __half* sAh = (const __half*)(dsm + s * P2_STAGE_B);
        const __half* sAl = sAh + TILE_E;
        const __half* sB  = sAl + TILE_E;

#pragma unroll
        for (int ks = 0; ks < 2; ks++) {
            wmma::fragment<wmma::matrix_a, 16, 16, 16, __half, wmma::row_major> afh[2], afl[2];
            wmma::fragment<wmma::matrix_b, 16, 16, 16, __half, wmma::col_major> bf[4];
#pragma unroll
            for (int i = 0; i < 2; i++) {
                wmma::load_matrix_sync(afh[i], sAh + (wm * 32 + i * 16) * GPITCH + ks * 16, GPITCH);
                wmma::load_matrix_sync(afl[i], sAl + (wm * 32 + i * 16) * GPITCH + ks * 16, GPITCH);
            }
#pragma unroll
            for (int j = 0; j < 4; j++)
                wmma::load_matrix_sync(bf[j], sB + (wn * 64 + j * 16) * GPITCH + ks * 16, GPITCH);
#pragma unroll
            for (int i = 0; i < 2; i++)
#pragma unroll
                for (int j = 0; j < 4; j++) {
                    wmma::mma_sync(acc[i][j], afh[i], bf[j], acc[i][j]);
                    wmma::mma_sync(acc[i][j], afl[i], bf[j], acc[i][j]);
                }
        }
        __syncthreads();
    }

    float* ep = (float*)dsm + w * (32 * 68);
#pragma unroll
    for (int i = 0; i < 2; i++)
#pragma unroll
        for (int j = 0; j < 4; j++)
            wmma::store_matrix_sync(ep + i * 16 * 68 + j * 16, acc[i][j], 68, wmma::mem_row_major);
    __syncwarp();

    const float* brow = bias + n0 + wn * 64;
    const size_t rowbase = (size_t)(m0 + wm * 32 + lane) * Dmod + n0 + wn * 64;
#pragma unroll
    for (int cc = 0; cc < 64; cc += 4) {
        float4 vv = *(const float4*)(ep + lane * 68 + cc);
        vv.x += brow[cc + 0];
        vv.y += brow[cc + 1];
        vv.z += brow[cc + 2];
        vv.w += brow[cc + 3];
        split_store4_f16(vv, outH + rowbase + cc, outL + rowbase + cc);
    }
}

// ---------------------------------------------------------------------------
// Attention: S = Qf16 @ Kf16^T (1 product), exp (FMA-pipe, x1024), P single
// fp16, O += P @ (Vh + Vl) (2 products). No max subtraction (scores tiny).
// Output: bf16 hi/lo, [B,H,N,Dh] contiguous. K/V double buffered.
// ---------------------------------------------------------------------------
#define QT 64
#define KTILE 64
#define APITCH 72
#define SPITCH 68
#define TB2 (64 * APITCH * 2)       // 9216 bytes per fp16 tile
#define SM_QF 0
#define SM_KF(s)  ((1 + (s)) * TB2)
#define SM_VH(s)  ((3 + (s)) * TB2)
#define SM_VL(s)  ((5 + (s)) * TB2)
#define SM_PH (7 * TB2)
#define SM_S  (8 * TB2)
#define ATTN_SMEM (8 * TB2 + 64 * SPITCH * 4)   // 91136

__global__ __launch_bounds__(128) void attn_tc_kernel()
{
    extern __shared__ char asm_[];
    const uint32_t sb = smem_u32(asm_);
    const int tid = threadIdx.x;
    const int w = tid >> 5;
    const int lane = tid & 31;
    const int bh = blockIdx.y;
    const int b = bh / Hh;
    const int h = bh % Hh;
    const int qRow0 = blockIdx.x * QT;

    const size_t headoff = (size_t)h * Dhd;
    const __half* q_g  = g_qf  + ((size_t)b * Nseq + qRow0) * Dmod + headoff;
    const __half* k_g  = g_kf  + (size_t)b * Nseq * Dmod + headoff;
    const __half* vh_g = g_vhf + (size_t)b * Nseq * Dmod + headoff;
    const __half* vl_g = g_vlf + (size_t)b * Nseq * Dmod + headoff;

    auto load_tile = [&](uint32_t dst, const __half* g) {
#pragma unroll
        for (int t = 0; t < 4; t++) {
            int id = tid + t * 128;
            int row = id >> 3;
            int c8 = (id & 7) * 8;
            cp16(dst + (uint32_t)(row * APITCH + c8) * 2, g + (size_t)row * Dmod + c8);
        }
    };

    load_tile(sb + SM_QF, q_g);
    load_tile(sb + SM_KF(0), k_g);
    load_tile(sb + SM_VH(0), vh_g);
    load_tile(sb + SM_VL(0), vl_g);
    CP_COMMIT();
    CP_WAIT0();
    __syncthreads();

    wmma::fragment<wmma::matrix_a, 16, 16, 16, __half, wmma::row_major> qf[4];
    {
        const __half* Qf = (const __half*)(asm_ + SM_QF) + w * 16 * APITCH;
#pragma unroll
        for (int ks = 0; ks < 4; ks++)
            wmma::load_matrix_sync(qf[ks], Qf + ks * 16, APITCH);
    }

    wmma::fragment<wmma::accumulator, 16, 16, 16, float> oacc[4];
#pragma unroll
    for (int dt = 0; dt < 4; dt++) wmma::fill_fragment(oacc[dt], 0.0f);

    const int rl = lane >> 1;
    const int c0 = (lane & 1) * 32;
    float lsum = 0.0f;

    float* Srow = (float*)(asm_ + SM_S) + (w * 16 + rl) * SPITCH + c0;
    __half* Ph_row = (__half*)(asm_ + SM_PH) + (w * 16 + rl) * APITCH + c0;

    const int NT = Nseq / KTILE;
    for (int kt = 0; kt < NT; kt++) {
        const int s = kt & 1;
        if (kt + 1 < NT) {
            const size_t koff = (size_t)(kt + 1) * KTILE * Dmod;
            load_tile(sb + SM_KF(s ^ 1), k_g + koff);
            load_tile(sb + SM_VH(s ^ 1), vh_g + koff);
            load_tile(sb + SM_VL(s ^ 1), vl_g + koff);
            CP_COMMIT();
        }

        // ---- S = Q @ K^T (warp-private 16x64 strip) ----
        const __half* Kf = (const __half*)(asm_ + SM_KF(s));
        float* Sst = (float*)(asm_ + SM_S) + (w * 16) * SPITCH;
#pragma unroll
        for (int jt = 0; jt < 4; jt++) {
            wmma::fragment<wmma::accumulator, 16, 16, 16, float> sacc;
            wmma::fill_fragment(sacc, 0.0f);
#pragma unroll
            for (int ks = 0; ks < 4; ks++) {
                wmma::fragment<wmma::matrix_b, 16, 16, 16, __half, wmma::col_major> kf;
                wmma::load_matrix_sync(kf, Kf + (jt * 16) * APITCH + ks * 16, APITCH);
                wmma::mma_sync(sacc, qf[ks], kf, sacc);
            }
            wmma::store_matrix_sync(Sst + jt * 16, sacc, SPITCH, wmma::mem_row_major);
        }
        __syncwarp();

        // ---- exp (x1024) + row-sum + P single fp16 ----
#pragma unroll
        for (int cc = 0; cc < 32; cc += 4) {
            float4 s4 = *(const float4*)(Srow + cc);
            float4 e4;
            e4.x = exp_fast_1024(s4.x);
            e4.y = exp_fast_1024(s4.y);
            e4.z = exp_fast_1024(s4.z);
            e4.w = exp_fast_1024(s4.w);
            lsum += (e4.x + e4.y) + (e4.z + e4.w);
            __half2 p01 = __floats2half2_rn(e4.x, e4.y);
            __half2 p23 = __floats2half2_rn(e4.z, e4.w);
            uint2 u;
            u.x = *(uint32_t*)&p01;
            u.y = *(uint32_t*)&p23;
            *(uint2*)(Ph_row + cc) = u;
        }
        __syncwarp();

        // ---- O += P @ (Vh + Vl) (2 products) ----
        const __half* Ph = (const __half*)(asm_ + SM_PH) + w * 16 * APITCH;
        const __half* Vh = (const __half*)(asm_ + SM_VH(s));
        const __half* Vl = (const __half*)(asm_ + SM_VL(s));
        wmma::fragment<wmma::matrix_a, 16, 16, 16, __half, wmma::row_major> pf[4];
#pragma unroll
        for (int kk = 0; kk < 4; kk++)
            wmma::load_matrix_sync(pf[kk], Ph + kk * 16, APITCH);
#pragma unroll
        for (int dt = 0; dt < 4; dt++) {
#pragma unroll
            for (int kk = 0; kk < 4; kk++) {
                wmma::fragment<wmma::matrix_b, 16, 16, 16, __half, wmma::row_major> vfh, vfl;
                wmma::load_matrix_sync(vfh, Vh + (kk * 16) * APITCH + dt * 16, APITCH);
                wmma::load_matrix_sync(vfl, Vl + (kk * 16) * APITCH + dt * 16, APITCH);
                wmma::mma_sync(oacc[dt], pf[kk], vfh, oacc[dt]);
                wmma::mma_sync(oacc[dt], pf[kk], vfl, oacc[dt]);
            }
        }

        if (kt + 1 < NT) CP_WAIT0();
        __syncthreads();
    }

    // ---- epilogue ----
    {
        float* Ost = (float*)(asm_ + SM_S) + (w * 16) * SPITCH;
#pragma unroll
        for (int dt = 0; dt < 4; dt++)
            wmma::store_matrix_sync(Ost + dt * 16, oacc[dt], SPITCH, wmma::mem_row_major);
    }
    __syncwarp();

    float ltot = lsum + __shfl_xor_sync(0xffffffffu, lsum, 1);
    float inv = 1.0f / ltot;

    const int n = qRow0 + w * 16 + rl;
    const size_t obase = (((size_t)bh * Nseq) + n) * Dhd + c0;
    const float* Orow = (float*)(asm_ + SM_S) + (w * 16 + rl) * SPITCH + c0;
#pragma unroll
    for (int cc = 0; cc < 32; cc += 4) {
        float4 v4 = *(const float4*)(Orow + cc);
        v4.x *= inv; v4.y *= inv; v4.z *= inv; v4.w *= inv;
        split_store4(v4, g_ohi + obase + cc, g_olo + obase + cc);
    }
}

// ---------------------------------------------------------------------------
extern "C" void kernel_launch(void* const* d_in, const int* in_sizes, int n_in,
                              void* d_out, int out_size)
{
    const float* x  = (const float*)d_in[0];
    const float* Wq = (const float*)d_in[1];
    const float* bq = (const float*)d_in[2];
    const float* Wk = (const float*)d_in[3];
    const float* bk = (const float*)d_in[4];
    const float* Wv = (const float*)d_in[5];
    const float* bv = (const float*)d_in[6];
    const float* Wc = (const float*)d_in[7];
    const float* bc = (const float*)d_in[8];
    float* out = (float*)d_out;

    __half *qf, *kf, *vhf, *vlf, *xhf, *xlf, *wqf, *wkf, *wvf;
    __nv_bfloat16 *ohi, *olo, *wchi, *wclo;
    cudaGetSymbolAddress((void**)&qf, g_qf);
    cudaGetSymbolAddress((void**)&kf, g_kf);
    cudaGetSymbolAddress((void**)&vhf, g_vhf);
    cudaGetSymbolAddress((void**)&vlf, g_vlf);
    cudaGetSymbolAddress((void**)&xhf, g_xhf);
    cudaGetSymbolAddress((void**)&xlf, g_xlf);
    cudaGetSymbolAddress((void**)&wqf, g_wqf);
    cudaGetSymbolAddress((void**)&wkf, g_wkf);
    cudaGetSymbolAddress((void**)&wvf, g_wvf);
    cudaGetSymbolAddress((void**)&ohi, g_ohi);
    cudaGetSymbolAddress((void**)&olo, g_olo);
    cudaGetSymbolAddress((void**)&wchi, g_wchi);
    cudaGetSymbolAddress((void**)&wclo, g_wclo);

    static bool attr_set = false;
    if (!attr_set) {
        cudaFuncSetAttribute(attn_tc_kernel,
                             cudaFuncAttributeMaxDynamicSharedMemorySize, ATTN_SMEM);
        cudaFuncSetAttribute(gemm_wmma,
                             cudaFuncAttributeMaxDynamicSharedMemorySize, BF3_SMEM);
        cudaFuncSetAttribute(gemm_f16,
                             cudaFuncAttributeMaxDynamicSharedMemorySize, F16_SMEM);
        cudaFuncSetAttribute(gemm_f16_2p,
                             cudaFuncAttributeMaxDynamicSharedMemorySize, P2_SMEM);
        attr_set = true;
    }

    const int n4x = Mtot * Dmod / 4;
    const int n4w = Dmod * Dmod / 4;
    split_f16_kernel<<<n4x / 256, 256>>>(x, xhf, xlf, n4x);
    tof16_kernel<<<n4w / 256, 256>>>(Wq, wqf, n4w);
    tof16_kernel<<<n4w / 256, 256>>>(Wk, wkf, n4w);
    tof16_kernel<<<n4w / 256, 256>>>(Wv, wvf, n4w);
    split_bf16_kernel<<<n4w / 256, 256>>>(Wc, wchi, wclo, n4w);

    dim3 gemm_grid(Dmod / 128, Mtot / 128);  // (8, 32)
    gemm_f16<<<gemm_grid, 256, F16_SMEM>>>(xhf, wqf, bq, qf, SCALE);
    gemm_f16<<<gemm_grid, 256, F16_SMEM>>>(xhf, wkf, bk, kf, 1.0f);
    gemm_f16_2p<<<gemm_grid, 256, P2_SMEM>>>(xhf, xlf, wvf, bv, vhf, vlf);

    dim3 attn_grid(Nseq / QT, Bsz * Hh);     // (16, 64)
    attn_tc_kernel<<<attn_grid, 128, ATTN_SMEM>>>();

    gemm_wmma<<<gemm_grid, 256, BF3_SMEM>>>(ohi, olo, wchi, wclo, bc, out);
}

// round 7
// speedup vs baseline: 3.4173x; 1.1519x over previous
#include <cuda_runtime.h>
#include <cuda_fp16.h>
#include <mma.h>
#include <math.h>
#include <stdint.h>

using namespace nvcuda;

#define Bsz 4
#define Nseq 1024
#define Dmod 1024
#define Hh 16
#define Dhd 64
#define Mtot (Bsz * Nseq)   // 4096
#define SCALE 0.03125f      // N^-0.5 = 1/32 (faithful quirk)

// ---------------------------------------------------------------------------
// Scratch (allocation-free rule: __device__ globals)
// ---------------------------------------------------------------------------
__device__ __half g_qf[Mtot * Dmod];      // fp16 q (pre-scaled by 1/32)
__device__ __half g_kf[Mtot * Dmod];      // fp16 k
__device__ __half g_vhf[Mtot * Dmod];     // fp16 v hi
__device__ __half g_vlf[Mtot * Dmod];     // fp16 v lo
__device__ __half g_xf[Mtot * Dmod];      // fp16 x
__device__ __half g_ohf[Mtot * Dmod];     // fp16 o hi ([B,H,N,Dh] contiguous)
__device__ __half g_olf[Mtot * Dmod];     // fp16 o lo
__device__ __half g_wqf[Dmod * Dmod];
__device__ __half g_wkf[Dmod * Dmod];
__device__ __half g_wvf[Dmod * Dmod];
__device__ __half g_wcf[Dmod * Dmod];

// ---------------------------------------------------------------------------
// helpers
// ---------------------------------------------------------------------------
__device__ __forceinline__ uint32_t smem_u32(const void* p) {
    uint32_t a;
    asm("{ .reg .u64 t; cvta.to.shared.u64 t, %1; cvt.u32.u64 %0, t; }"
        : "=r"(a) : "l"(p));
    return a;
}
__device__ __forceinline__ void cp16(uint32_t saddr, const void* g) {
    asm volatile("cp.async.cg.shared.global [%0], [%1], 16;" :: "r"(saddr), "l"(g));
}
#define CP_COMMIT() asm volatile("cp.async.commit_group;" ::: "memory")
#define CP_WAIT0()  asm volatile("cp.async.wait_group 0;" ::: "memory")
#define CP_WAIT1()  asm volatile("cp.async.wait_group 1;" ::: "memory")

// fast exp on FMA pipe, result scaled by 2^10
__device__ __forceinline__ float exp_fast_1024(float x) {
    float y = x * 1.44269504088896f;
    float z = y + 12582912.0f;
    int   n = __float_as_int(z) - 0x4B400000;
    float r = z - 12582912.0f;
    float t = y - r;
    float p =            0.00015403530393381609f;
    p = fmaf(p, t, 0.0013333558146428443f);
    p = fmaf(p, t, 0.009618129107628477f);
    p = fmaf(p, t, 0.05550410866482158f);
    p = fmaf(p, t, 0.2402265069591007f);
    p = fmaf(p, t, 0.6931471805599453f);
    p = fmaf(p, t, 1.0f);
    return __int_as_float(__float_as_int(p) + ((n + 10) << 23));
}

// fp16 hi/lo split store
__device__ __forceinline__ void split_store4_f16(float4 v, __half* hp, __half* lp) {
    __half h0 = __float2half_rn(v.x);
    __half h1 = __float2half_rn(v.y);
    __half h2 = __float2half_rn(v.z);
    __half h3 = __float2half_rn(v.w);
    __half2 hh01 = __halves2half2(h0, h1);
    __half2 hh23 = __halves2half2(h2, h3);
    uint2 h;
    h.x = *(uint32_t*)&hh01;
    h.y = *(uint32_t*)&hh23;
    *(uint2*)hp = h;
    __half2 ll01 = __floats2half2_rn(v.x - __half2float(h0), v.y - __half2float(h1));
    __half2 ll23 = __floats2half2_rn(v.z - __half2float(h2), v.w - __half2float(h3));
    uint2 l;
    l.x = *(uint32_t*)&ll01;
    l.y = *(uint32_t*)&ll23;
    *(uint2*)lp = l;
}

__global__ __launch_bounds__(256) void tof16_kernel(
    const float* __restrict__ src, __half* __restrict__ dst, int n4)
{
    int i = blockIdx.x * blockDim.x + threadIdx.x;
    if (i >= n4) return;
    float4 v = ((const float4*)src)[i];
    __half2 h01 = __floats2half2_rn(v.x, v.y);
    __half2 h23 = __floats2half2_rn(v.z, v.w);
    uint2 u;
    u.x = *(uint32_t*)&h01;
    u.y = *(uint32_t*)&h23;
    ((uint2*)dst)[i] = u;
}

// ---------------------------------------------------------------------------
// common GEMM tile constants
// ---------------------------------------------------------------------------
#define GPITCH 40
#define TILE_E (128 * GPITCH)
#define TILE_B (TILE_E * 2)              // 10240 bytes
#define NSTAGE (Dmod / 32)               // 32

// ---------------------------------------------------------------------------
// fp16 single-product NT GEMM (Q/K/V projections)
// epilogue: fp16 scaled (Cf16) OR fp16 hi/lo split (outH/outL)
// ---------------------------------------------------------------------------
#define F16_STAGE_B (2 * TILE_B)          // 20480
#define F16_SMEM 69632

__global__ __launch_bounds__(256) void gemm_f16(
    const __half* __restrict__ A, const __half* __restrict__ B,
    const float* __restrict__ bias,
    __half* __restrict__ Cf16,
    __half* __restrict__ outH, __half* __restrict__ outL,
    float oscale)
{
    extern __shared__ char dsm[];
    const int tid = threadIdx.x;
    const int w = tid >> 5;
    const int lane = tid & 31;
    const int m0 = blockIdx.y * 128;
    const int n0 = blockIdx.x * 128;
    const int wm = w >> 1;
    const int wn = w & 1;

    const uint32_t sb = smem_u32(dsm);
    const int lrow = tid >> 1;
    const int v0 = (tid & 1) * 2;

    const __half* ag = A + (size_t)(m0 + lrow) * Dmod;
    const __half* bg = B + (size_t)(n0 + lrow) * Dmod;

    wmma::fragment<wmma::accumulator, 16, 16, 16, float> acc[2][4];
#pragma unroll
    for (int i = 0; i < 2; i++)
#pragma unroll
        for (int j = 0; j < 4; j++) wmma::fill_fragment(acc[i][j], 0.0f);

    auto load_stage = [&](int c, int s) {
        const int kc0 = c * 32;
        const uint32_t st = sb + s * F16_STAGE_B;
#pragma unroll
        for (int vv = 0; vv < 2; vv++) {
            int v = v0 + vv;
            uint32_t so = (uint32_t)(lrow * (GPITCH * 2) + v * 16);
            cp16(st + so, ag + kc0 + v * 8);
            cp16(st + TILE_B + so, bg + kc0 + v * 8);
        }
        CP_COMMIT();
    };

    load_stage(0, 0);

    for (int c = 0; c < NSTAGE; c++) {
        const int s = c & 1;
        if (c + 1 < NSTAGE) {
            load_stage(c + 1, s ^ 1);
            CP_WAIT1();
        } else {
            CP_WAIT0();
        }
        __syncthreads();

        const __half* sA = (const __half*)(dsm + s * F16_STAGE_B);
        const __half* sB = sA + TILE_E;

#pragma unroll
        for (int ks = 0; ks < 2; ks++) {
            wmma::fragment<wmma::matrix_a, 16, 16, 16, __half, wmma::row_major> af[2];
            wmma::fragment<wmma::matrix_b, 16, 16, 16, __half, wmma::col_major> bf[4];
#pragma unroll
            for (int i = 0; i < 2; i++)
                wmma::load_matrix_sync(af[i], sA + (wm * 32 + i * 16) * GPITCH + ks * 16, GPITCH);
#pragma unroll
            for (int j = 0; j < 4; j++)
                wmma::load_matrix_sync(bf[j], sB + (wn * 64 + j * 16) * GPITCH + ks * 16, GPITCH);
#pragma unroll
            for (int i = 0; i < 2; i++)
#pragma unroll
                for (int j = 0; j < 4; j++)
                    wmma::mma_sync(acc[i][j], af[i], bf[j], acc[i][j]);
        }
        __syncthreads();
    }

    float* ep = (float*)dsm + w * (32 * 68);
#pragma unroll
    for (int i = 0; i < 2; i++)
#pragma unroll
        for (int j = 0; j < 4; j++)
            wmma::store_matrix_sync(ep + i * 16 * 68 + j * 16, acc[i][j], 68, wmma::mem_row_major);
    __syncwarp();

    const float* brow = bias + n0 + wn * 64;
    const size_t rowbase = (size_t)(m0 + wm * 32 + lane) * Dmod + n0 + wn * 64;

    if (Cf16 != nullptr) {
        __half* crow = Cf16 + rowbase;
#pragma unroll
        for (int cc = 0; cc < 64; cc += 4) {
            float4 vv = *(const float4*)(ep + lane * 68 + cc);
            vv.x = (vv.x + brow[cc + 0]) * oscale;
            vv.y = (vv.y + brow[cc + 1]) * oscale;
            vv.z = (vv.z + brow[cc + 2]) * oscale;
            vv.w = (vv.w + brow[cc + 3]) * oscale;
            __half2 h01 = __floats2half2_rn(vv.x, vv.y);
            __half2 h23 = __floats2half2_rn(vv.z, vv.w);
            uint2 u;
            u.x = *(uint32_t*)&h01;
            u.y = *(uint32_t*)&h23;
            *(uint2*)(crow + cc) = u;
        }
    } else {
#pragma unroll
        for (int cc = 0; cc < 64; cc += 4) {
            float4 vv = *(const float4*)(ep + lane * 68 + cc);
            vv.x += brow[cc + 0];
            vv.y += brow[cc + 1];
            vv.z += brow[cc + 2];
            vv.w += brow[cc + 3];
            split_store4_f16(vv, outH + rowbase + cc, outL + rowbase + cc);
        }
    }
}

// ---------------------------------------------------------------------------
// fp16 2-product NT GEMM (output projection): C = (Ahi+Alo) @ B^T + bias, fp32 out
// ---------------------------------------------------------------------------
#define P2_STAGE_B (3 * TILE_B)           // 30720
#define P2_SMEM 69632

__global__ __launch_bounds__(256) void gemm_f16_2p(
    const __half* __restrict__ Ahi, const __half* __restrict__ Alo,
    const __half* __restrict__ B,
    const float* __restrict__ bias, float* __restrict__ Cf)
{
    extern __shared__ char dsm[];
    const int tid = threadIdx.x;
    const int w = tid >> 5;
    const int lane = tid & 31;
    const int m0 = blockIdx.y * 128;
    const int n0 = blockIdx.x * 128;
    const int wm = w >> 1;
    const int wn = w & 1;

    const uint32_t sb = smem_u32(dsm);
    const int lrow = tid >> 1;
    const int v0 = (tid & 1) * 2;

    const __half* ah = Ahi + (size_t)(m0 + lrow) * Dmod;
    const __half* al = Alo + (size_t)(m0 + lrow) * Dmod;
    const __half* bg = B   + (size_t)(n0 + lrow) * Dmod;

    wmma::fragment<wmma::accumulator, 16, 16, 16, float> acc[2][4];
#pragma unroll
    for (int i = 0; i < 2; i++)
#pragma unroll
        for (int j = 0; j < 4; j++) wmma::fill_fragment(acc[i][j], 0.0f);

    auto load_stage = [&](int c, int s) {
        const int kc0 = c * 32;
        const uint32_t st = sb + s * P2_STAGE_B;
#pragma unroll
        for (int vv = 0; vv < 2; vv++) {
            int v = v0 + vv;
            uint32_t so = (uint32_t)(lrow * (GPITCH * 2) + v * 16);
            cp16(st + 0 * TILE_B + so, ah + kc0 + v * 8);
            cp16(st + 1 * TILE_B + so, al + kc0 + v * 8);
            cp16(st + 2 * TILE_B + so, bg + kc0 + v * 8);
        }
        CP_COMMIT();
    };

    load_stage(0, 0);

    for (int c = 0; c < NSTAGE; c++) {
        const int s = c & 1;
        if (c + 1 < NSTAGE) {
            load_stage(c + 1, s ^ 1);
            CP_WAIT1();
        } else {
            CP_WAIT0();
        }
        __syncthreads();

        const __half* sAh = (const __half*)(dsm + s * P2_STAGE_B);
        const __half* sAl = sAh + TILE_E;
        const __half* sB  = sAl + TILE_E;

#pragma unroll
        for (int ks = 0; ks < 2; ks++) {
            wmma::fragment<wmma::matrix_a, 16, 16, 16, __half, wmma::row_major> afh[2], afl[2];
            wmma::fragment<wmma::matrix_b, 16, 16, 16, __half, wmma::col_major> bf[4];
#pragma unroll
            for (int i = 0; i < 2; i++) {
                wmma::load_matrix_sync(afh[i], sAh + (wm * 32 + i * 16) * GPITCH + ks * 16, GPITCH);
                wmma::load_matrix_sync(afl[i], sAl + (wm * 32 + i * 16) * GPITCH + ks * 16, GPITCH);
            }
#pragma unroll
            for (int j = 0; j < 4; j++)
                wmma::load_matrix_sync(bf[j], sB + (wn * 64 + j * 16) * GPITCH + ks * 16, GPITCH);
#pragma unroll
            for (int i = 0; i < 2; i++)
#pragma unroll
                for (int j = 0; j < 4; j++) {
                    wmma::mma_sync(acc[i][j], afh[i], bf[j], acc[i][j]);
                    wmma::mma_sync(acc[i][j], afl[i], bf[j], acc[i][j]);
                }
        }
        __syncthreads();
    }

    float* ep = (float*)dsm + w * (32 * 68);
#pragma unroll
    for (int i = 0; i < 2; i++)
#pragma unroll
        for (int j = 0; j < 4; j++)
            wmma::store_matrix_sync(ep + i * 16 * 68 + j * 16, acc[i][j], 68, wmma::mem_row_major);
    __syncwarp();

    const float* brow = bias + n0 + wn * 64;
    float* crow = Cf + (size_t)(m0 + wm * 32 + lane) * Dmod + n0 + wn * 64;
#pragma unroll
    for (int cc = 0; cc < 64; cc += 4) {
        float4 vv = *(const float4*)(ep + lane * 68 + cc);
        vv.x += brow[cc + 0];
        vv.y += brow[cc + 1];
        vv.z += brow[cc + 2];
        vv.w += brow[cc + 3];
        *(float4*)(crow + cc) = vv;
    }
}

// ---------------------------------------------------------------------------
// Attention: QT=128 (8 warps). S = Q@K^T (1 product), exp (FMA pipe, x1024),
// P fp16, O += P @ (Vh+Vl) (2 products). No max subtraction (scores tiny by
// the 1/32 quirk). Output fp16 hi/lo, [B,H,N,Dh] contiguous. K/V dbl-buffered.
// ---------------------------------------------------------------------------
#define QT 128
#define KTILE 64
#define APITCH 72
#define SPITCH 68
#define TB64 (64 * APITCH * 2)       // 9216 bytes per 64-row fp16 tile
#define SM_QF 0                      // 128 rows: 18432
#define SM_KF(s)  (18432 + (s) * TB64)
#define SM_VH(s)  (36864 + (s) * TB64)
#define SM_VL(s)  (55296 + (s) * TB64)
#define SM_PH 73728                  // 128 rows: 18432
#define SM_S  92160                  // 128 x 68 f32: 34816
#define ATTN_SMEM 126976

__global__ __launch_bounds__(256) void attn_tc_kernel()
{
    extern __shared__ char asm_[];
    const uint32_t sb = smem_u32(asm_);
    const int tid = threadIdx.x;
    const int w = tid >> 5;          // 0..7
    const int lane = tid & 31;
    const int bh = blockIdx.y;
    const int b = bh / Hh;
    const int h = bh % Hh;
    const int qRow0 = blockIdx.x * QT;

    const size_t headoff = (size_t)h * Dhd;
    const __half* q_g  = g_qf  + ((size_t)b * Nseq + qRow0) * Dmod + headoff;
    const __half* k_g  = g_kf  + (size_t)b * Nseq * Dmod + headoff;
    const __half* vh_g = g_vhf + (size_t)b * Nseq * Dmod + headoff;
    const __half* vl_g = g_vlf + (size_t)b * Nseq * Dmod + headoff;

    // 64-row tile loader (K/V): 2 x 256 threads x 16B
    auto load_tile64 = [&](uint32_t dst, const __half* g) {
#pragma unroll
        for (int t = 0; t < 2; t++) {
            int id = tid + t * 256;
            int row = id >> 3;
            int c8 = (id & 7) * 8;
            cp16(dst + (uint32_t)(row * APITCH + c8) * 2, g + (size_t)row * Dmod + c8);
        }
    };
    // 128-row Q loader
    auto load_q = [&]() {
#pragma unroll
        for (int t = 0; t < 4; t++) {
            int id = tid + t * 256;
            int row = id >> 3;
            int c8 = (id & 7) * 8;
            cp16(sb + SM_QF + (uint32_t)(row * APITCH + c8) * 2, q_g + (size_t)row * Dmod + c8);
        }
    };

    load_q();
    load_tile64(sb + SM_KF(0), k_g);
    load_tile64(sb + SM_VH(0), vh_g);
    load_tile64(sb + SM_VL(0), vl_g);
    CP_COMMIT();
    CP_WAIT0();
    __syncthreads();

    // hoist Q fragments (warp strip rows [16w, 16w+16))
    wmma::fragment<wmma::matrix_a, 16, 16, 16, __half, wmma::row_major> qf[4];
    {
        const __half* Qf = (const __half*)(asm_ + SM_QF) + w * 16 * APITCH;
#pragma unroll
        for (int ks = 0; ks < 4; ks++)
            wmma::load_matrix_sync(qf[ks], Qf + ks * 16, APITCH);
    }

    wmma::fragment<wmma::accumulator, 16, 16, 16, float> oacc[4];
#pragma unroll
    for (int dt = 0; dt < 4; dt++) wmma::fill_fragment(oacc[dt], 0.0f);

    const int rl = lane >> 1;
    const int c0 = (lane & 1) * 32;
    float lsum = 0.0f;

    float* Srow = (float*)(asm_ + SM_S) + (w * 16 + rl) * SPITCH + c0;
    __half* Ph_row = (__half*)(asm_ + SM_PH) + (w * 16 + rl) * APITCH + c0;

    const int NT = Nseq / KTILE;     // 16
    for (int kt = 0; kt < NT; kt++) {
        const int s = kt & 1;
        if (kt + 1 < NT) {
            const size_t koff = (size_t)(kt + 1) * KTILE * Dmod;
            load_tile64(sb + SM_KF(s ^ 1), k_g + koff);
            load_tile64(sb + SM_VH(s ^ 1), vh_g + koff);
            load_tile64(sb + SM_VL(s ^ 1), vl_g + koff);
            CP_COMMIT();
        }

        // ---- S = Q @ K^T (warp-private 16x64 strip) ----
        const __half* Kf = (const __half*)(asm_ + SM_KF(s));
        float* Sst = (float*)(asm_ + SM_S) + (w * 16) * SPITCH;
#pragma unroll
        for (int jt = 0; jt < 4; jt++) {
            wmma::fragment<wmma::accumulator, 16, 16, 16, float> sacc;
            wmma::fill_fragment(sacc, 0.0f);
#pragma unroll
            for (int ks = 0; ks < 4; ks++) {
                wmma::fragment<wmma::matrix_b, 16, 16, 16, __half, wmma::col_major> kf;
                wmma::load_matrix_sync(kf, Kf + (jt * 16) * APITCH + ks * 16, APITCH);
                wmma::mma_sync(sacc, qf[ks], kf, sacc);
            }
            wmma::store_matrix_sync(Sst + jt * 16, sacc, SPITCH, wmma::mem_row_major);
        }
        __syncwarp();

        // ---- exp (x1024) + row-sum + P fp16 ----
#pragma unroll
        for (int cc = 0; cc < 32; cc += 4) {
            float4 s4 = *(const float4*)(Srow + cc);
            float4 e4;
            e4.x = exp_fast_1024(s4.x);
            e4.y = exp_fast_1024(s4.y);
            e4.z = exp_fast_1024(s4.z);
            e4.w = exp_fast_1024(s4.w);
            lsum += (e4.x + e4.y) + (e4.z + e4.w);
            __half2 p01 = __floats2half2_rn(e4.x, e4.y);
            __half2 p23 = __floats2half2_rn(e4.z, e4.w);
            uint2 u;
            u.x = *(uint32_t*)&p01;
            u.y = *(uint32_t*)&p23;
            *(uint2*)(Ph_row + cc) = u;
        }
        __syncwarp();

        // ---- O += P @ (Vh + Vl) (2 products) ----
        const __half* Ph = (const __half*)(asm_ + SM_PH) + w * 16 * APITCH;
        const __half* Vh = (const __half*)(asm_ + SM_VH(s));
        const __half* Vl = (const __half*)(asm_ + SM_VL(s));
        wmma::fragment<wmma::matrix_a, 16, 16, 16, __half, wmma::row_major> pf[4];
#pragma unroll
        for (int kk = 0; kk < 4; kk++)
            wmma::load_matrix_sync(pf[kk], Ph + kk * 16, APITCH);
#pragma unroll
        for (int dt = 0; dt < 4; dt++) {
#pragma unroll
            for (int kk = 0; kk < 4; kk++) {
                wmma::fragment<wmma::matrix_b, 16, 16, 16, __half, wmma::row_major> vfh, vfl;
                wmma::load_matrix_sync(vfh, Vh + (kk * 16) * APITCH + dt * 16, APITCH);
                wmma::load_matrix_sync(vfl, Vl + (kk * 16) * APITCH + dt * 16, APITCH);
                wmma::mma_sync(oacc[dt], pf[kk], vfh, oacc[dt]);
                wmma::mma_sync(oacc[dt], pf[kk], vfl, oacc[dt]);
            }
        }

        if (kt + 1 < NT) {
            CP_WAIT0();
            __syncthreads();
        }
    }

    // ---- epilogue: stage O, normalize by row sum, fp16 hi/lo split store ----
    {
        float* Ost = (float*)(asm_ + SM_S) + (w * 16) * SPITCH;
#pragma unroll
        for (int dt = 0; dt < 4; dt++)
            wmma::store_matrix_sync(Ost + dt * 16, oacc[dt], SPITCH, wmma::mem_row_major);
    }
    __syncwarp();

    float ltot = lsum + __shfl_xor_sync(0xffffffffu, lsum, 1);
    float inv = 1.0f / ltot;

    const int n = qRow0 + w * 16 + rl;
    const size_t obase = (((size_t)bh * Nseq) + n) * Dhd + c0;
    const float* Orow = (float*)(asm_ + SM_S) + (w * 16 + rl) * SPITCH + c0;
#pragma unroll
    for (int cc = 0; cc < 32; cc += 4) {
        float4 v4 = *(const float4*)(Orow + cc);
        v4.x *= inv; v4.y *= inv; v4.z *= inv; v4.w *= inv;
        split_store4_f16(v4, g_ohf + obase + cc, g_olf + obase + cc);
    }
}

// ---------------------------------------------------------------------------
extern "C" void kernel_launch(void* const* d_in, const int* in_sizes, int n_in,
                              void* d_out, int out_size)
{
    const float* x  = (const float*)d_in[0];
    const float* Wq = (const float*)d_in[1];
    const float* bq = (const float*)d_in[2];
    const float* Wk = (const float*)d_in[3];
    const float* bk = (const float*)d_in[4];
    const float* Wv = (const float*)d_in[5];
    const float* bv = (const float*)d_in[6];
    const float* Wc = (const float*)d_in[7];
    const float* bc = (const float*)d_in[8];
    float* out = (float*)d_out;

    __half *qf, *kf, *vhf, *vlf, *xf, *ohf, *olf, *wqf, *wkf, *wvf, *wcf;
    cudaGetSymbolAddress((void**)&qf, g_qf);
    cudaGetSymbolAddress((void**)&kf, g_kf);
    cudaGetSymbolAddress((void**)&vhf, g_vhf);
    cudaGetSymbolAddress((void**)&vlf, g_vlf);
    cudaGetSymbolAddress((void**)&xf, g_xf);
    cudaGetSymbolAddress((void**)&ohf, g_ohf);
    cudaGetSymbolAddress((void**)&olf, g_olf);
    cudaGetSymbolAddress((void**)&wqf, g_wqf);
    cudaGetSymbolAddress((void**)&wkf, g_wkf);
    cudaGetSymbolAddress((void**)&wvf, g_wvf);
    cudaGetSymbolAddress((void**)&wcf, g_wcf);

    static bool attr_set = false;
    if (!attr_set) {
        cudaFuncSetAttribute(attn_tc_kernel,
                             cudaFuncAttributeMaxDynamicSharedMemorySize, ATTN_SMEM);
        cudaFuncSetAttribute(gemm_f16,
                             cudaFuncAttributeMaxDynamicSharedMemorySize, F16_SMEM);
        cudaFuncSetAttribute(gemm_f16_2p,
                             cudaFuncAttributeMaxDynamicSharedMemorySize, P2_SMEM);
        attr_set = true;
    }

    const int n4x = Mtot * Dmod / 4;
    const int n4w = Dmod * Dmod / 4;
    tof16_kernel<<<n4x / 256, 256>>>(x,  xf,  n4x);
    tof16_kernel<<<n4w / 256, 256>>>(Wq, wqf, n4w);
    tof16_kernel<<<n4w / 256, 256>>>(Wk, wkf, n4w);
    tof16_kernel<<<n4w / 256, 256>>>(Wv, wvf, n4w);
    tof16_kernel<<<n4w / 256, 256>>>(Wc, wcf, n4w);

    dim3 gemm_grid(Dmod / 128, Mtot / 128);  // (8, 32)
    gemm_f16<<<gemm_grid, 256, F16_SMEM>>>(xf, wqf, bq, qf, nullptr, nullptr, SCALE);
    gemm_f16<<<gemm_grid, 256, F16_SMEM>>>(xf, wkf, bk, kf, nullptr, nullptr, 1.0f);
    gemm_f16<<<gemm_grid, 256, F16_SMEM>>>(xf, wvf, bv, nullptr, vhf, vlf, 1.0f);

    dim3 attn_grid(Nseq / QT, Bsz * Hh);     // (8, 64)
    attn_tc_kernel<<<attn_grid, 256, ATTN_SMEM>>>();

    gemm_f16_2p<<<gemm_grid, 256, P2_SMEM>>>(ohf, olf, wcf, bc, out);
}

// round 8
// speedup vs baseline: 4.5991x; 1.3458x over previous
#include <cuda_runtime.h>
#include <cuda_fp16.h>
#include <mma.h>
#include <math.h>
#include <stdint.h>

using namespace nvcuda;

#define Bsz 4
#define Nseq 1024
#define Dmod 1024
#define Hh 16
#define Dhd 64
#define Mtot (Bsz * Nseq)   // 4096
#define SCALE 0.03125f      // N^-0.5 = 1/32 (faithful quirk)

// ---------------------------------------------------------------------------
// Scratch (allocation-free rule: __device__ globals)
// ---------------------------------------------------------------------------
__device__ __half g_qf[Mtot * Dmod];      // fp16 q (pre-scaled by 1/32)
__device__ __half g_kf[Mtot * Dmod];      // fp16 k
__device__ __half g_vf[Mtot * Dmod];      // fp16 v
__device__ __half g_xf[Mtot * Dmod];      // fp16 x
__device__ __half g_of[Mtot * Dmod];      // fp16 o ([B,H,N,Dh] contiguous)
__device__ __half g_wqf[Dmod * Dmod];
__device__ __half g_wkf[Dmod * Dmod];
__device__ __half g_wvf[Dmod * Dmod];
__device__ __half g_wcf[Dmod * Dmod];

// ---------------------------------------------------------------------------
// helpers
// ---------------------------------------------------------------------------
__device__ __forceinline__ uint32_t smem_u32(const void* p) {
    uint32_t a;
    asm("{ .reg .u64 t; cvta.to.shared.u64 t, %1; cvt.u32.u64 %0, t; }"
        : "=r"(a) : "l"(p));
    return a;
}
__device__ __forceinline__ void cp16(uint32_t saddr, const void* g) {
    asm volatile("cp.async.cg.shared.global [%0], [%1], 16;" :: "r"(saddr), "l"(g));
}
#define CP_COMMIT() asm volatile("cp.async.commit_group;" ::: "memory")
#define CP_WAIT0()  asm volatile("cp.async.wait_group 0;" ::: "memory")
#define CP_WAIT1()  asm volatile("cp.async.wait_group 1;" ::: "memory")

// fast exp on FMA pipe, result scaled by 2^10
__device__ __forceinline__ float exp_fast_1024(float x) {
    float y = x * 1.44269504088896f;
    float z = y + 12582912.0f;
    int   n = __float_as_int(z) - 0x4B400000;
    float r = z - 12582912.0f;
    float t = y - r;
    float p =            0.00015403530393381609f;
    p = fmaf(p, t, 0.0013333558146428443f);
    p = fmaf(p, t, 0.009618129107628477f);
    p = fmaf(p, t, 0.05550410866482158f);
    p = fmaf(p, t, 0.2402265069591007f);
    p = fmaf(p, t, 0.6931471805599453f);
    p = fmaf(p, t, 1.0f);
    return __int_as_float(__float_as_int(p) + ((n + 10) << 23));
}

// ---------------------------------------------------------------------------
// fused fp32 -> fp16 convert: x (4096 blocks) + 4 weights (1024 blocks each)
// ---------------------------------------------------------------------------
__global__ __launch_bounds__(256) void convert_all_kernel(
    const float* __restrict__ x,  __half* __restrict__ xf,
    const float* __restrict__ w0, __half* __restrict__ w0f,
    const float* __restrict__ w1, __half* __restrict__ w1f,
    const float* __restrict__ w2, __half* __restrict__ w2f,
    const float* __restrict__ w3, __half* __restrict__ w3f)
{
    int bid = blockIdx.x;
    const float* src;
    __half* dst;
    int i;
    if (bid < 4096) {
        src = x; dst = xf;
        i = bid * 256 + threadIdx.x;
    } else {
        int t = bid - 4096;
        int wsel = t >> 10;
        src = (wsel == 0) ? w0 : (wsel == 1) ? w1 : (wsel == 2) ? w2 : w3;
        dst = (wsel == 0) ? w0f : (wsel == 1) ? w1f : (wsel == 2) ? w2f : w3f;
        i = (t & 1023) * 256 + threadIdx.x;
    }
    float4 v = ((const float4*)src)[i];
    __half2 h01 = __floats2half2_rn(v.x, v.y);
    __half2 h23 = __floats2half2_rn(v.z, v.w);
    uint2 u;
    u.x = *(uint32_t*)&h01;
    u.y = *(uint32_t*)&h23;
    ((uint2*)dst)[i] = u;
}

// ---------------------------------------------------------------------------
// common GEMM tile constants
// ---------------------------------------------------------------------------
#define GPITCH 40
#define TILE_E (128 * GPITCH)
#define TILE_B (TILE_E * 2)              // 10240 bytes
#define NSTAGE (Dmod / 32)               // 32

// ---------------------------------------------------------------------------
// fp16 single-product NT GEMM: C = A @ B^T + bias
// epilogue: fp16 scaled (Cf16) OR fp32 (Cf32)
// ---------------------------------------------------------------------------
#define F16_STAGE_B (2 * TILE_B)          // 20480
#define F16_SMEM 69632

__global__ __launch_bounds__(256) void gemm_f16(
    const __half* __restrict__ A, const __half* __restrict__ B,
    const float* __restrict__ bias,
    __half* __restrict__ Cf16, float* __restrict__ Cf32,
    float oscale)
{
    extern __shared__ char dsm[];
    const int tid = threadIdx.x;
    const int w = tid >> 5;
    const int lane = tid & 31;
    const int m0 = blockIdx.y * 128;
    const int n0 = blockIdx.x * 128;
    const int wm = w >> 1;
    const int wn = w & 1;

    const uint32_t sb = smem_u32(dsm);
    const int lrow = tid >> 1;
    const int v0 = (tid & 1) * 2;

    const __half* ag = A + (size_t)(m0 + lrow) * Dmod;
    const __half* bg = B + (size_t)(n0 + lrow) * Dmod;

    wmma::fragment<wmma::accumulator, 16, 16, 16, float> acc[2][4];
#pragma unroll
    for (int i = 0; i < 2; i++)
#pragma unroll
        for (int j = 0; j < 4; j++) wmma::fill_fragment(acc[i][j], 0.0f);

    auto load_stage = [&](int c, int s) {
        const int kc0 = c * 32;
        const uint32_t st = sb + s * F16_STAGE_B;
#pragma unroll
        for (int vv = 0; vv < 2; vv++) {
            int v = v0 + vv;
            uint32_t so = (uint32_t)(lrow * (GPITCH * 2) + v * 16);
            cp16(st + so, ag + kc0 + v * 8);
            cp16(st + TILE_B + so, bg + kc0 + v * 8);
        }
        CP_COMMIT();
    };

    load_stage(0, 0);

    for (int c = 0; c < NSTAGE; c++) {
        const int s = c & 1;
        if (c + 1 < NSTAGE) {
            load_stage(c + 1, s ^ 1);
            CP_WAIT1();
        } else {
            CP_WAIT0();
        }
        __syncthreads();

        const __half* sA = (const __half*)(dsm + s * F16_STAGE_B);
        const __half* sB = sA + TILE_E;

#pragma unroll
        for (int ks = 0; ks < 2; ks++) {
            wmma::fragment<wmma::matrix_a, 16, 16, 16, __half, wmma::row_major> af[2];
            wmma::fragment<wmma::matrix_b, 16, 16, 16, __half, wmma::col_major> bf[4];
#pragma unroll
            for (int i = 0; i < 2; i++)
                wmma::load_matrix_sync(af[i], sA + (wm * 32 + i * 16) * GPITCH + ks * 16, GPITCH);
#pragma unroll
            for (int j = 0; j < 4; j++)
                wmma::load_matrix_sync(bf[j], sB + (wn * 64 + j * 16) * GPITCH + ks * 16, GPITCH);
#pragma unroll
            for (int i = 0; i < 2; i++)
#pragma unroll
                for (int j = 0; j < 4; j++)
                    wmma::mma_sync(acc[i][j], af[i], bf[j], acc[i][j]);
        }
        __syncthreads();
    }

    float* ep = (float*)dsm + w * (32 * 68);
#pragma unroll
    for (int i = 0; i < 2; i++)
#pragma unroll
        for (int j = 0; j < 4; j++)
            wmma::store_matrix_sync(ep + i * 16 * 68 + j * 16, acc[i][j], 68, wmma::mem_row_major);
    __syncwarp();

    const float* brow = bias + n0 + wn * 64;
    const size_t rowbase = (size_t)(m0 + wm * 32 + lane) * Dmod + n0 + wn * 64;

    if (Cf32 != nullptr) {
        float* crow = Cf32 + rowbase;
#pragma unroll
        for (int cc = 0; cc < 64; cc += 4) {
            float4 vv = *(const float4*)(ep + lane * 68 + cc);
            vv.x += brow[cc + 0];
            vv.y += brow[cc + 1];
            vv.z += brow[cc + 2];
            vv.w += brow[cc + 3];
            *(float4*)(crow + cc) = vv;
        }
    } else {
        __half* crow = Cf16 + rowbase;
#pragma unroll
        for (int cc = 0; cc < 64; cc += 4) {
            float4 vv = *(const float4*)(ep + lane * 68 + cc);
            vv.x = (vv.x + brow[cc + 0]) * oscale;
            vv.y = (vv.y + brow[cc + 1]) * oscale;
            vv.z = (vv.z + brow[cc + 2]) * oscale;
            vv.w = (vv.w + brow[cc + 3]) * oscale;
            __half2 h01 = __floats2half2_rn(vv.x, vv.y);
            __half2 h23 = __floats2half2_rn(vv.z, vv.w);
            uint2 u;
            u.x = *(uint32_t*)&h01;
            u.y = *(uint32_t*)&h23;
            *(uint2*)(crow + cc) = u;
        }
    }
}

// ---------------------------------------------------------------------------
// Attention: QT=128 (8 warps, 2 CTAs/SM). S = Q@K^T (1 product), exp (FMA
// pipe, x1024), P fp16, O += P@V (1 product). No max subtraction (scores
// tiny by the 1/32 quirk). Output plain fp16, [B,H,N,Dh] contiguous.
// K/V double buffered.
// ---------------------------------------------------------------------------
#define QT 128
#define KTILE 64
#define APITCH 72
#define SPITCH 68
#define TB64 (64 * APITCH * 2)       // 9216 bytes per 64-row fp16 tile
#define SM_QF 0                      // 128 rows: 18432
#define SM_KF(s)  (18432 + (s) * TB64)
#define SM_VF(s)  (36864 + (s) * TB64)
#define SM_PH 55296                  // 128 rows: 18432
#define SM_S  73728                  // 128 x 68 f32: 34816
#define ATTN_SMEM 108544

__global__ __launch_bounds__(256) void attn_tc_kernel()
{
    extern __shared__ char asm_[];
    const uint32_t sb = smem_u32(asm_);
    const int tid = threadIdx.x;
    const int w = tid >> 5;          // 0..7
    const int lane = tid & 31;
    const int bh = blockIdx.y;
    const int b = bh / Hh;
    const int h = bh % Hh;
    const int qRow0 = blockIdx.x * QT;

    const size_t headoff = (size_t)h * Dhd;
    const __half* q_g = g_qf + ((size_t)b * Nseq + qRow0) * Dmod + headoff;
    const __half* k_g = g_kf + (size_t)b * Nseq * Dmod + headoff;
    const __half* v_g = g_vf + (size_t)b * Nseq * Dmod + headoff;

    auto load_tile64 = [&](uint32_t dst, const __half* g) {
#pragma unroll
        for (int t = 0; t < 2; t++) {
            int id = tid + t * 256;
            int row = id >> 3;
            int c8 = (id & 7) * 8;
            cp16(dst + (uint32_t)(row * APITCH + c8) * 2, g + (size_t)row * Dmod + c8);
        }
    };
    auto load_q = [&]() {
#pragma unroll
        for (int t = 0; t < 4; t++) {
            int id = tid + t * 256;
            int row = id >> 3;
            int c8 = (id & 7) * 8;
            cp16(sb + SM_QF + (uint32_t)(row * APITCH + c8) * 2, q_g + (size_t)row * Dmod + c8);
        }
    };

    load_q();
    load_tile64(sb + SM_KF(0), k_g);
    load_tile64(sb + SM_VF(0), v_g);
    CP_COMMIT();
    CP_WAIT0();
    __syncthreads();

    // hoist Q fragments (warp strip rows [16w, 16w+16))
    wmma::fragment<wmma::matrix_a, 16, 16, 16, __half, wmma::row_major> qf[4];
    {
        const __half* Qf = (const __half*)(asm_ + SM_QF) + w * 16 * APITCH;
#pragma unroll
        for (int ks = 0; ks < 4; ks++)
            wmma::load_matrix_sync(qf[ks], Qf + ks * 16, APITCH);
    }

    wmma::fragment<wmma::accumulator, 16, 16, 16, float> oacc[4];
#pragma unroll
    for (int dt = 0; dt < 4; dt++) wmma::fill_fragment(oacc[dt], 0.0f);

    const int rl = lane >> 1;
    const int c0 = (lane & 1) * 32;
    float lsum = 0.0f;

    float* Srow = (float*)(asm_ + SM_S) + (w * 16 + rl) * SPITCH + c0;
    __half* Ph_row = (__half*)(asm_ + SM_PH) + (w * 16 + rl) * APITCH + c0;

    const int NT = Nseq / KTILE;     // 16
    for (int kt = 0; kt < NT; kt++) {
        const int s = kt & 1;
        if (kt + 1 < NT) {
            const size_t koff = (size_t)(kt + 1) * KTILE * Dmod;
            load_tile64(sb + SM_KF(s ^ 1), k_g + koff);
            load_tile64(sb + SM_VF(s ^ 1), v_g + koff);
            CP_COMMIT();
        }

        // ---- S = Q @ K^T (warp-private 16x64 strip) ----
        const __half* Kf = (const __half*)(asm_ + SM_KF(s));
        float* Sst = (float*)(asm_ + SM_S) + (w * 16) * SPITCH;
#pragma unroll
        for (int jt = 0; jt < 4; jt++) {
            wmma::fragment<wmma::accumulator, 16, 16, 16, float> sacc;
            wmma::fill_fragment(sacc, 0.0f);
#pragma unroll
            for (int ks = 0; ks < 4; ks++) {
                wmma::fragment<wmma::matrix_b, 16, 16, 16, __half, wmma::col_major> kf;
                wmma::load_matrix_sync(kf, Kf + (jt * 16) * APITCH + ks * 16, APITCH);
                wmma::mma_sync(sacc, qf[ks], kf, sacc);
            }
            wmma::store_matrix_sync(Sst + jt * 16, sacc, SPITCH, wmma::mem_row_major);
        }
        __syncwarp();

        // ---- exp (x1024) + row-sum + P fp16 ----
#pragma unroll
        for (int cc = 0; cc < 32; cc += 4) {
            float4 s4 = *(const float4*)(Srow + cc);
            float4 e4;
            e4.x = exp_fast_1024(s4.x);
            e4.y = exp_fast_1024(s4.y);
            e4.z = exp_fast_1024(s4.z);
            e4.w = exp_fast_1024(s4.w);
            lsum += (e4.x + e4.y) + (e4.z + e4.w);
            __half2 p01 = __floats2half2_rn(e4.x, e4.y);
            __half2 p23 = __floats2half2_rn(e4.z, e4.w);
            uint2 u;
            u.x = *(uint32_t*)&p01;
            u.y = *(uint32_t*)&p23;
            *(uint2*)(Ph_row + cc) = u;
        }
        __syncwarp();

        // ---- O += P @ V (single product) ----
        const __half* Ph = (const __half*)(asm_ + SM_PH) + w * 16 * APITCH;
        const __half* Vf = (const __half*)(asm_ + SM_VF(s));
        wmma::fragment<wmma::matrix_a, 16, 16, 16, __half, wmma::row_major> pf[4];
#pragma unroll
        for (int kk = 0; kk < 4; kk++)
            wmma::load_matrix_sync(pf[kk], Ph + kk * 16, APITCH);
#pragma unroll
        for (int dt = 0; dt < 4; dt++) {
#pragma unroll
            for (int kk = 0; kk < 4; kk++) {
                wmma::fragment<wmma::matrix_b, 16, 16, 16, __half, wmma::row_major> vf;
                wmma::load_matrix_sync(vf, Vf + (kk * 16) * APITCH + dt * 16, APITCH);
                wmma::mma_sync(oacc[dt], pf[kk], vf, oacc[dt]);
            }
        }

        if (kt + 1 < NT) {
            CP_WAIT0();
            __syncthreads();
        }
    }

    // ---- epilogue: stage O, normalize, plain fp16 store ----
    {
        float* Ost = (float*)(asm_ + SM_S) + (w * 16) * SPITCH;
#pragma unroll
        for (int dt = 0; dt < 4; dt++)
            wmma::store_matrix_sync(Ost + dt * 16, oacc[dt], SPITCH, wmma::mem_row_major);
    }
    __syncwarp();

    float ltot = lsum + __shfl_xor_sync(0xffffffffu, lsum, 1);
    float inv = 1.0f / ltot;

    const int n = qRow0 + w * 16 + rl;
    const size_t obase = (((size_t)bh * Nseq) + n) * Dhd + c0;
    const float* Orow = (float*)(asm_ + SM_S) + (w * 16 + rl) * SPITCH + c0;
#pragma unroll
    for (int cc = 0; cc < 32; cc += 4) {
        float4 v4 = *(const float4*)(Orow + cc);
        __half2 h01 = __floats2half2_rn(v4.x * inv, v4.y * inv);
        __half2 h23 = __floats2half2_rn(v4.z * inv, v4.w * inv);
        uint2 u;
        u.x = *(uint32_t*)&h01;
        u.y = *(uint32_t*)&h23;
        *(uint2*)(g_of + obase + cc) = u;
    }
}

// ---------------------------------------------------------------------------
extern "C" void kernel_launch(void* const* d_in, const int* in_sizes, int n_in,
                              void* d_out, int out_size)
{
    const float* x  = (const float*)d_in[0];
    const float* Wq = (const float*)d_in[1];
    const float* bq = (const float*)d_in[2];
    const float* Wk = (const float*)d_in[3];
    const float* bk = (const float*)d_in[4];
    const float* Wv = (const float*)d_in[5];
    const float* bv = (const float*)d_in[6];
    const float* Wc = (const float*)d_in[7];
    const float* bc = (const float*)d_in[8];
    float* out = (float*)d_out;

    __half *qf, *kf, *vf, *xf, *of, *wqf, *wkf, *wvf, *wcf;
    cudaGetSymbolAddress((void**)&qf, g_qf);
    cudaGetSymbolAddress((void**)&kf, g_kf);
    cudaGetSymbolAddress((void**)&vf, g_vf);
    cudaGetSymbolAddress((void**)&xf, g_xf);
    cudaGetSymbolAddress((void**)&of, g_of);
    cudaGetSymbolAddress((void**)&wqf, g_wqf);
    cudaGetSymbolAddress((void**)&wkf, g_wkf);
    cudaGetSymbolAddress((void**)&wvf, g_wvf);
    cudaGetSymbolAddress((void**)&wcf, g_wcf);

    static bool attr_set = false;
    if (!attr_set) {
        cudaFuncSetAttribute(attn_tc_kernel,
                             cudaFuncAttributeMaxDynamicSharedMemorySize, ATTN_SMEM);
        cudaFuncSetAttribute(gemm_f16,
                             cudaFuncAttributeMaxDynamicSharedMemorySize, F16_SMEM);
        attr_set = true;
    }

    // fused converts: x (4096 blocks) + Wq/Wk/Wv/Wc (1024 blocks each)
    convert_all_kernel<<<4096 + 4 * 1024, 256>>>(
        x, xf, Wq, wqf, Wk, wkf, Wv, wvf, Wc, wcf);

    dim3 gemm_grid(Dmod / 128, Mtot / 128);  // (8, 32)
    gemm_f16<<<gemm_grid, 256, F16_SMEM>>>(xf, wqf, bq, qf, nullptr, SCALE);
    gemm_f16<<<gemm_grid, 256, F16_SMEM>>>(xf, wkf, bk, kf, nullptr, 1.0f);
    gemm_f16<<<gemm_grid, 256, F16_SMEM>>>(xf, wvf, bv, vf, nullptr, 1.0f);

    dim3 attn_grid(Nseq / QT, Bsz * Hh);     // (8, 64)
    attn_tc_kernel<<<attn_grid, 256, ATTN_SMEM>>>();

    gemm_f16<<<gemm_grid, 256, F16_SMEM>>>(of, wcf, bc, nullptr, out, 1.0f);
}

// round 9
// speedup vs baseline: 4.8469x; 1.0539x over previous
#include <cuda_runtime.h>
#include <cuda_fp16.h>
#include <mma.h>
#include <math.h>
#include <stdint.h>

using namespace nvcuda;

#define Bsz 4
#define Nseq 1024
#define Dmod 1024
#define Hh 16
#define Dhd 64
#define Mtot (Bsz * Nseq)   // 4096
#define SCALE 0.03125f      // N^-0.5 = 1/32 (faithful quirk)

// ---------------------------------------------------------------------------
// Scratch (allocation-free rule: __device__ globals)
// ---------------------------------------------------------------------------
__device__ __half g_qf[Mtot * Dmod];      // fp16 q (pre-scaled by 1/32)
__device__ __half g_kf[Mtot * Dmod];      // fp16 k
__device__ __half g_vf[Mtot * Dmod];      // fp16 v
__device__ __half g_xf[Mtot * Dmod];      // fp16 x
__device__ __half g_of[Mtot * Dmod];      // fp16 o ([B,H,N,Dh] contiguous)
__device__ __half g_wqf[Dmod * Dmod];
__device__ __half g_wkf[Dmod * Dmod];
__device__ __half g_wvf[Dmod * Dmod];
__device__ __half g_wcf[Dmod * Dmod];

// ---------------------------------------------------------------------------
// helpers
// ---------------------------------------------------------------------------
__device__ __forceinline__ uint32_t smem_u32(const void* p) {
    uint32_t a;
    asm("{ .reg .u64 t; cvta.to.shared.u64 t, %1; cvt.u32.u64 %0, t; }"
        : "=r"(a) : "l"(p));
    return a;
}
__device__ __forceinline__ void cp16(uint32_t saddr, const void* g) {
    asm volatile("cp.async.cg.shared.global [%0], [%1], 16;" :: "r"(saddr), "l"(g));
}
#define CP_COMMIT() asm volatile("cp.async.commit_group;" ::: "memory")
#define CP_WAIT0()  asm volatile("cp.async.wait_group 0;" ::: "memory")
#define CP_WAIT2()  asm volatile("cp.async.wait_group 2;" ::: "memory")

// fast exp on FMA pipe, result scaled by 2^10
__device__ __forceinline__ float exp_fast_1024(float x) {
    float y = x * 1.44269504088896f;
    float z = y + 12582912.0f;
    int   n = __float_as_int(z) - 0x4B400000;
    float r = z - 12582912.0f;
    float t = y - r;
    float p =            0.00015403530393381609f;
    p = fmaf(p, t, 0.0013333558146428443f);
    p = fmaf(p, t, 0.009618129107628477f);
    p = fmaf(p, t, 0.05550410866482158f);
    p = fmaf(p, t, 0.2402265069591007f);
    p = fmaf(p, t, 0.6931471805599453f);
    p = fmaf(p, t, 1.0f);
    return __int_as_float(__float_as_int(p) + ((n + 10) << 23));
}

// ---------------------------------------------------------------------------
// fused fp32 -> fp16 convert: x (4096 blocks) + 4 weights (1024 blocks each)
// ---------------------------------------------------------------------------
__global__ __launch_bounds__(256) void convert_all_kernel(
    const float* __restrict__ x,  __half* __restrict__ xf,
    const float* __restrict__ w0, __half* __restrict__ w0f,
    const float* __restrict__ w1, __half* __restrict__ w1f,
    const float* __restrict__ w2, __half* __restrict__ w2f,
    const float* __restrict__ w3, __half* __restrict__ w3f)
{
    int bid = blockIdx.x;
    const float* src;
    __half* dst;
    int i;
    if (bid < 4096) {
        src = x; dst = xf;
        i = bid * 256 + threadIdx.x;
    } else {
        int t = bid - 4096;
        int wsel = t >> 10;
        src = (wsel == 0) ? w0 : (wsel == 1) ? w1 : (wsel == 2) ? w2 : w3;
        dst = (wsel == 0) ? w0f : (wsel == 1) ? w1f : (wsel == 2) ? w2f : w3f;
        i = (t & 1023) * 256 + threadIdx.x;
    }
    float4 v = ((const float4*)src)[i];
    __half2 h01 = __floats2half2_rn(v.x, v.y);
    __half2 h23 = __floats2half2_rn(v.z, v.w);
    uint2 u;
    u.x = *(uint32_t*)&h01;
    u.y = *(uint32_t*)&h23;
    ((uint2*)dst)[i] = u;
}

// ---------------------------------------------------------------------------
// common GEMM tile constants
// ---------------------------------------------------------------------------
#define GPITCH 40
#define TILE_E (128 * GPITCH)
#define TILE_B (TILE_E * 2)              // 10240 bytes
#define NSTAGE (Dmod / 32)               // 32 K-chunks
#define NPIPE 4
#define STAGE_B (2 * TILE_B)             // 20480 per pipeline stage
#define GEMM_SMEM (NPIPE * STAGE_B)      // 81920

// ---------------------------------------------------------------------------
// fp16 single-product NT GEMM core (4-stage cp.async pipeline)
// ---------------------------------------------------------------------------
struct GemmOut {
    __half* f16;      // fp16 output (scaled), or null
    float*  f32;      // fp32 output, or null
    float   oscale;
};

__device__ __forceinline__ void gemm_f16_core(
    const __half* __restrict__ A, const __half* __restrict__ B,
    const float* __restrict__ bias, GemmOut outd,
    int m0, int n0, char* dsm)
{
    const int tid = threadIdx.x;
    const int w = tid >> 5;
    const int lane = tid & 31;
    const int wm = w >> 1;
    const int wn = w & 1;

    const uint32_t sb = smem_u32(dsm);
    const int lrow = tid >> 1;
    const int v0 = (tid & 1) * 2;

    const __half* ag = A + (size_t)(m0 + lrow) * Dmod;
    const __half* bg = B + (size_t)(n0 + lrow) * Dmod;

    wmma::fragment<wmma::accumulator, 16, 16, 16, float> acc[2][4];
#pragma unroll
    for (int i = 0; i < 2; i++)
#pragma unroll
        for (int j = 0; j < 4; j++) wmma::fill_fragment(acc[i][j], 0.0f);

    auto load_stage = [&](int c, int s) {
        const int kc0 = c * 32;
        const uint32_t st = sb + s * STAGE_B;
#pragma unroll
        for (int vv = 0; vv < 2; vv++) {
            int v = v0 + vv;
            uint32_t so = (uint32_t)(lrow * (GPITCH * 2) + v * 16);
            cp16(st + so, ag + kc0 + v * 8);
            cp16(st + TILE_B + so, bg + kc0 + v * 8);
        }
    };

    // prologue: stages 0..2 in flight
#pragma unroll
    for (int c = 0; c < NPIPE - 1; c++) {
        load_stage(c, c);
        CP_COMMIT();
    }

    for (int c = 0; c < NSTAGE; c++) {
        const int s = c & (NPIPE - 1);
        CP_WAIT2();                 // stage c complete (<=2 younger pending)
        __syncthreads();

        const __half* sA = (const __half*)(dsm + s * STAGE_B);
        const __half* sB = sA + TILE_E;

#pragma unroll
        for (int ks = 0; ks < 2; ks++) {
            wmma::fragment<wmma::matrix_a, 16, 16, 16, __half, wmma::row_major> af[2];
            wmma::fragment<wmma::matrix_b, 16, 16, 16, __half, wmma::col_major> bf[4];
#pragma unroll
            for (int i = 0; i < 2; i++)
                wmma::load_matrix_sync(af[i], sA + (wm * 32 + i * 16) * GPITCH + ks * 16, GPITCH);
#pragma unroll
            for (int j = 0; j < 4; j++)
                wmma::load_matrix_sync(bf[j], sB + (wn * 64 + j * 16) * GPITCH + ks * 16, GPITCH);
#pragma unroll
            for (int i = 0; i < 2; i++)
#pragma unroll
                for (int j = 0; j < 4; j++)
                    wmma::mma_sync(acc[i][j], af[i], bf[j], acc[i][j]);
        }

        if (c + NPIPE - 1 < NSTAGE)
            load_stage(c + NPIPE - 1, (c + NPIPE - 1) & (NPIPE - 1));
        CP_COMMIT();                // always commit (possibly empty group)
    }
    __syncthreads();                // all compute done before epilogue reuses smem

    float* ep = (float*)dsm + w * (32 * 68);
#pragma unroll
    for (int i = 0; i < 2; i++)
#pragma unroll
        for (int j = 0; j < 4; j++)
            wmma::store_matrix_sync(ep + i * 16 * 68 + j * 16, acc[i][j], 68, wmma::mem_row_major);
    __syncwarp();

    const float* brow = bias + n0 + wn * 64;
    const size_t rowbase = (size_t)(m0 + wm * 32 + lane) * Dmod + n0 + wn * 64;

    if (outd.f32 != nullptr) {
        float* crow = outd.f32 + rowbase;
#pragma unroll
        for (int cc = 0; cc < 64; cc += 4) {
            float4 vv = *(const float4*)(ep + lane * 68 + cc);
            vv.x += brow[cc + 0];
            vv.y += brow[cc + 1];
            vv.z += brow[cc + 2];
            vv.w += brow[cc + 3];
            *(float4*)(crow + cc) = vv;
        }
    } else {
        __half* crow = outd.f16 + rowbase;
#pragma unroll
        for (int cc = 0; cc < 64; cc += 4) {
            float4 vv = *(const float4*)(ep + lane * 68 + cc);
            vv.x = (vv.x + brow[cc + 0]) * outd.oscale;
            vv.y = (vv.y + brow[cc + 1]) * outd.oscale;
            vv.z = (vv.z + brow[cc + 2]) * outd.oscale;
            vv.w = (vv.w + brow[cc + 3]) * outd.oscale;
            __half2 h01 = __floats2half2_rn(vv.x, vv.y);
            __half2 h23 = __floats2half2_rn(vv.z, vv.w);
            uint2 u;
            u.x = *(uint32_t*)&h01;
            u.y = *(uint32_t*)&h23;
            *(uint2*)(crow + cc) = u;
        }
    }
}

// fused Q/K/V projection: grid.z selects weight/bias/output
__global__ __launch_bounds__(256) void gemm_qkv(
    const __half* __restrict__ X,
    const __half* __restrict__ Wq, const float* __restrict__ bq,
    const __half* __restrict__ Wk, const float* __restrict__ bk,
    const __half* __restrict__ Wv, const float* __restrict__ bv,
    __half* __restrict__ Q, __half* __restrict__ K, __half* __restrict__ V)
{
    extern __shared__ char dsm[];
    const int z = blockIdx.z;
    const __half* B = (z == 0) ? Wq : (z == 1) ? Wk : Wv;
    const float* bias = (z == 0) ? bq : (z == 1) ? bk : bv;
    GemmOut o;
    o.f16 = (z == 0) ? Q : (z == 1) ? K : V;
    o.f32 = nullptr;
    o.oscale = (z == 0) ? SCALE : 1.0f;
    gemm_f16_core(X, B, bias, o, blockIdx.y * 128, blockIdx.x * 128, dsm);
}

// output projection: fp32 out
__global__ __launch_bounds__(256) void gemm_out(
    const __half* __restrict__ O, const __half* __restrict__ Wc,
    const float* __restrict__ bc, float* __restrict__ out)
{
    extern __shared__ char dsm[];
    GemmOut o;
    o.f16 = nullptr;
    o.f32 = out;
    o.oscale = 1.0f;
    gemm_f16_core(O, Wc, bc, o, blockIdx.y * 128, blockIdx.x * 128, dsm);
}

// ---------------------------------------------------------------------------
// Attention: QT=128 (8 warps, 2 CTAs/SM). S = Q@K^T (1 product), exp (FMA
// pipe, x1024), P fp16, O += P@V (1 product). No max subtraction (scores
// tiny by the 1/32 quirk). Output plain fp16, [B,H,N,Dh] contiguous.
// K/V double buffered.
// ---------------------------------------------------------------------------
#define QT 128
#define KTILE 64
#define APITCH 72
#define SPITCH 68
#define TB64 (64 * APITCH * 2)       // 9216 bytes per 64-row fp16 tile
#define SM_QF 0                      // 128 rows: 18432
#define SM_KF(s)  (18432 + (s) * TB64)
#define SM_VF(s)  (36864 + (s) * TB64)
#define SM_PH 55296                  // 128 rows: 18432
#define SM_S  73728                  // 128 x 68 f32: 34816
#define ATTN_SMEM 108544

__global__ __launch_bounds__(256) void attn_tc_kernel()
{
    extern __shared__ char asm_[];
    const uint32_t sb = smem_u32(asm_);
    const int tid = threadIdx.x;
    const int w = tid >> 5;          // 0..7
    const int lane = tid & 31;
    const int bh = blockIdx.y;
    const int b = bh / Hh;
    const int h = bh % Hh;
    const int qRow0 = blockIdx.x * QT;

    const size_t headoff = (size_t)h * Dhd;
    const __half* q_g = g_qf + ((size_t)b * Nseq + qRow0) * Dmod + headoff;
    const __half* k_g = g_kf + (size_t)b * Nseq * Dmod + headoff;
    const __half* v_g = g_vf + (size_t)b * Nseq * Dmod + headoff;

    auto load_tile64 = [&](uint32_t dst, const __half* g) {
#pragma unroll
        for (int t = 0; t < 2; t++) {
            int id = tid + t * 256;
            int row = id >> 3;
            int c8 = (id & 7) * 8;
            cp16(dst + (uint32_t)(row * APITCH + c8) * 2, g + (size_t)row * Dmod + c8);
        }
    };
    auto load_q = [&]() {
#pragma unroll
        for (int t = 0; t < 4; t++) {
            int id = tid + t * 256;
            int row = id >> 3;
            int c8 = (id & 7) * 8;
            cp16(sb + SM_QF + (uint32_t)(row * APITCH + c8) * 2, q_g + (size_t)row * Dmod + c8);
        }
    };

    load_q();
    load_tile64(sb + SM_KF(0), k_g);
    load_tile64(sb + SM_VF(0), v_g);
    CP_COMMIT();
    CP_WAIT0();
    __syncthreads();

    wmma::fragment<wmma::matrix_a, 16, 16, 16, __half, wmma::row_major> qf[4];
    {
        const __half* Qf = (const __half*)(asm_ + SM_QF) + w * 16 * APITCH;
#pragma unroll
        for (int ks = 0; ks < 4; ks++)
            wmma::load_matrix_sync(qf[ks], Qf + ks * 16, APITCH);
    }

    wmma::fragment<wmma::accumulator, 16, 16, 16, float> oacc[4];
#pragma unroll
    for (int dt = 0; dt < 4; dt++) wmma::fill_fragment(oacc[dt], 0.0f);

    const int rl = lane >> 1;
    const int c0 = (lane & 1) * 32;
    float lsum = 0.0f;

    float* Srow = (float*)(asm_ + SM_S) + (w * 16 + rl) * SPITCH + c0;
    __half* Ph_row = (__half*)(asm_ + SM_PH) + (w * 16 + rl) * APITCH + c0;

    const int NT = Nseq / KTILE;     // 16
    for (int kt = 0; kt < NT; kt++) {
        const int s = kt & 1;
        if (kt + 1 < NT) {
            const size_t koff = (size_t)(kt + 1) * KTILE * Dmod;
            load_tile64(sb + SM_KF(s ^ 1), k_g + koff);
            load_tile64(sb + SM_VF(s ^ 1), v_g + koff);
            CP_COMMIT();
        }

        // ---- S = Q @ K^T (warp-private 16x64 strip) ----
        const __half* Kf = (const __half*)(asm_ + SM_KF(s));
        float* Sst = (float*)(asm_ + SM_S) + (w * 16) * SPITCH;
#pragma unroll
        for (int jt = 0; jt < 4; jt++) {
            wmma::fragment<wmma::accumulator, 16, 16, 16, float> sacc;
            wmma::fill_fragment(sacc, 0.0f);
#pragma unroll
            for (int ks = 0; ks < 4; ks++) {
                wmma::fragment<wmma::matrix_b, 16, 16, 16, __half, wmma::col_major> kf;
                wmma::load_matrix_sync(kf, Kf + (jt * 16) * APITCH + ks * 16, APITCH);
                wmma::mma_sync(sacc, qf[ks], kf, sacc);
            }
            wmma::store_matrix_sync(Sst + jt * 16, sacc, SPITCH, wmma::mem_row_major);
        }
        __syncwarp();

        // ---- exp (x1024) + row-sum + P fp16 ----
#pragma unroll
        for (int cc = 0; cc < 32; cc += 4) {
            float4 s4 = *(const float4*)(Srow + cc);
            float4 e4;
            e4.x = exp_fast_1024(s4.x);
            e4.y = exp_fast_1024(s4.y);
            e4.z = exp_fast_1024(s4.z);
            e4.w = exp_fast_1024(s4.w);
            lsum += (e4.x + e4.y) + (e4.z + e4.w);
            __half2 p01 = __floats2half2_rn(e4.x, e4.y);
            __half2 p23 = __floats2half2_rn(e4.z, e4.w);
            uint2 u;
            u.x = *(uint32_t*)&p01;
            u.y = *(uint32_t*)&p23;
            *(uint2*)(Ph_row + cc) = u;
        }
        __syncwarp();

        // ---- O += P @ V (single product) ----
        const __half* Ph = (const __half*)(asm_ + SM_PH) + w * 16 * APITCH;
        const __half* Vf = (const __half*)(asm_ + SM_VF(s));
        wmma::fragment<wmma::matrix_a, 16, 16, 16, __half, wmma::row_major> pf[4];
#pragma unroll
        for (int kk = 0; kk < 4; kk++)
            wmma::load_matrix_sync(pf[kk], Ph + kk * 16, APITCH);
#pragma unroll
        for (int dt = 0; dt < 4; dt++) {
#pragma unroll
            for (int kk = 0; kk < 4; kk++) {
                wmma::fragment<wmma::matrix_b, 16, 16, 16, __half, wmma::row_major> vf;
                wmma::load_matrix_sync(vf, Vf + (kk * 16) * APITCH + dt * 16, APITCH);
                wmma::mma_sync(oacc[dt], pf[kk], vf, oacc[dt]);
            }
        }

        if (kt + 1 < NT) {
            CP_WAIT0();
            __syncthreads();
        }
    }

    // ---- epilogue ----
    {
        float* Ost = (float*)(asm_ + SM_S) + (w * 16) * SPITCH;
#pragma unroll
        for (int dt = 0; dt < 4; dt++)
            wmma::store_matrix_sync(Ost + dt * 16, oacc[dt], SPITCH, wmma::mem_row_major);
    }
    __syncwarp();

    float ltot = lsum + __shfl_xor_sync(0xffffffffu, lsum, 1);
    float inv = 1.0f / ltot;

    const int n = qRow0 + w * 16 + rl;
    const size_t obase = (((size_t)bh * Nseq) + n) * Dhd + c0;
    const float* Orow = (float*)(asm_ + SM_S) + (w * 16 + rl) * SPITCH + c0;
#pragma unroll
    for (int cc = 0; cc < 32; cc += 4) {
        float4 v4 = *(const float4*)(Orow + cc);
        __half2 h01 = __floats2half2_rn(v4.x * inv, v4.y * inv);
        __half2 h23 = __floats2half2_rn(v4.z * inv, v4.w * inv);
        uint2 u;
        u.x = *(uint32_t*)&h01;
        u.y = *(uint32_t*)&h23;
        *(uint2*)(g_of + obase + cc) = u;
    }
}

// ---------------------------------------------------------------------------
extern "C" void kernel_launch(void* const* d_in, const int* in_sizes, int n_in,
                              void* d_out, int out_size)
{
    const float* x  = (const float*)d_in[0];
    const float* Wq = (const float*)d_in[1];
    const float* bq = (const float*)d_in[2];
    const float* Wk = (const float*)d_in[3];
    const float* bk = (const float*)d_in[4];
    const float* Wv = (const float*)d_in[5];
    const float* bv = (const float*)d_in[6];
    const float* Wc = (const float*)d_in[7];
    const float* bc = (const float*)d_in[8];
    float* out = (float*)d_out;

    __half *qf, *kf, *vf, *xf, *of, *wqf, *wkf, *wvf, *wcf;
    cudaGetSymbolAddress((void**)&qf, g_qf);
    cudaGetSymbolAddress((void**)&kf, g_kf);
    cudaGetSymbolAddress((void**)&vf, g_vf);
    cudaGetSymbolAddress((void**)&xf, g_xf);
    cudaGetSymbolAddress((void**)&of, g_of);
    cudaGetSymbolAddress((void**)&wqf, g_wqf);
    cudaGetSymbolAddress((void**)&wkf, g_wkf);
    cudaGetSymbolAddress((void**)&wvf, g_wvf);
    cudaGetSymbolAddress((void**)&wcf, g_wcf);

    static bool attr_set = false;
    if (!attr_set) {
        cudaFuncSetAttribute(attn_tc_kernel,
                             cudaFuncAttributeMaxDynamicSharedMemorySize, ATTN_SMEM);
        cudaFuncSetAttribute(gemm_qkv,
                             cudaFuncAttributeMaxDynamicSharedMemorySize, GEMM_SMEM);
        cudaFuncSetAttribute(gemm_out,
                             cudaFuncAttributeMaxDynamicSharedMemorySize, GEMM_SMEM);
        attr_set = true;
    }

    convert_all_kernel<<<4096 + 4 * 1024, 256>>>(
        x, xf, Wq, wqf, Wk, wkf, Wv, wvf, Wc, wcf);

    dim3 qkv_grid(Dmod / 128, Mtot / 128, 3);   // (8, 32, 3) = 768 CTAs
    gemm_qkv<<<qkv_grid, 256, GEMM_SMEM>>>(xf, wqf, bq, wkf, bk, wvf, bv,
                                           qf, kf, vf);

    dim3 attn_grid(Nseq / QT, Bsz * Hh);        // (8, 64)
    attn_tc_kernel<<<attn_grid, 256, ATTN_SMEM>>>();

    dim3 out_grid(Dmod / 128, Mtot / 128);      // (8, 32)
    gemm_out<<<out_grid, 256, GEMM_SMEM>>>(of, wcf, bc, out);
}